// round 9
// baseline (speedup 1.0000x reference)
#include <cuda_runtime.h>
#include <cuda_bf16.h>
#include <cstdint>

#define NB 16
#define LL 512
#define EE 256
#define FF 256
#define MM 4096
#define OUT_ELEMS (NB * MM * EE)   // 16777216
#define KTOT 768
#define NROWS (NB * LL)            // 8192
#define KC 64                      // K chunk (bf16)
#define NCHUNK (KTOT / KC)         // 12
#define PADK 72                    // padded row length (bf16) -> 144 B
#define ROWB (PADK * 2)            // 144 bytes

// ---------------- scratch (hi/lo bf16 planes for 3xBF16 compensation) --------
__device__ __nv_bfloat16 g_xh1[NROWS * KTOT];
__device__ __nv_bfloat16 g_xl1[NROWS * KTOT];
__device__ __nv_bfloat16 g_xh2[NROWS * KTOT];
__device__ __nv_bfloat16 g_xl2[NROWS * KTOT];
__device__ __nv_bfloat16 g_h1h[NROWS * FF];
__device__ __nv_bfloat16 g_h1l[NROWS * FF];
__device__ __nv_bfloat16 g_wh1[FF * KTOT];
__device__ __nv_bfloat16 g_wl1[FF * KTOT];
__device__ __nv_bfloat16 g_wh2[FF * KTOT];
__device__ __nv_bfloat16 g_wl2[FF * KTOT];
__device__ int           g_idx[NB * MM];

// ---------------- smem layout ----------------
#define ASZ   (128 * ROWB)             // A_hi rows 0-63, A_lo rows 64-127
#define BSZ   (512 * ROWB)             // B_hi rows 0-255, B_lo rows 256-511
#define STAGE (ASZ + BSZ)              // 92160
#define SM_PAR (2 * STAGE)             // 184320
#define SM_TOTAL (SM_PAR + 4096)       // 188416

// ---------------- helpers ----------------
__device__ __forceinline__ uint32_t smem_u32(const void* p) {
    uint32_t a;
    asm("{ .reg .u64 t; cvta.to.shared.u64 t, %1; cvt.u32.u64 %0, t; }" : "=r"(a) : "l"(p));
    return a;
}
__device__ __forceinline__ void cp16(uint32_t dst, const void* src) {
    asm volatile("cp.async.cg.shared.global [%0], [%1], 16;" :: "r"(dst), "l"(src));
}
#define CP_COMMIT() asm volatile("cp.async.commit_group;" ::: "memory")
template <int N>
__device__ __forceinline__ void cp_wait() {
    asm volatile("cp.async.wait_group %0;" :: "n"(N) : "memory");
}
__device__ __forceinline__ void ldsm4(uint32_t* r, uint32_t addr) {
    asm volatile("ldmatrix.sync.aligned.m8n8.x4.shared.b16 {%0,%1,%2,%3}, [%4];"
                 : "=r"(r[0]), "=r"(r[1]), "=r"(r[2]), "=r"(r[3]) : "r"(addr));
}
__device__ __forceinline__ void mma_bf16(float* d, uint32_t a0, uint32_t a1,
                                         uint32_t a2, uint32_t a3,
                                         uint32_t b0, uint32_t b1) {
    asm volatile(
        "mma.sync.aligned.m16n8k16.row.col.f32.bf16.bf16.f32 "
        "{%0,%1,%2,%3}, {%4,%5,%6,%7}, {%8,%9}, {%0,%1,%2,%3};"
        : "+f"(d[0]), "+f"(d[1]), "+f"(d[2]), "+f"(d[3])
        : "r"(a0), "r"(a1), "r"(a2), "r"(a3), "r"(b0), "r"(b1));
}
__device__ __forceinline__ void split_bf16(float v, __nv_bfloat16& hi, __nv_bfloat16& lo) {
    hi = __float2bfloat16(v);
    lo = __float2bfloat16(v - __bfloat162float(hi));
}

// ---------------- weight prep ----------------
__global__ void prep_w_kernel(const float* __restrict__ w1, const float* __restrict__ w2) {
    int f = blockIdx.x;
    const float* w = blockIdx.y ? w2 : w1;
    __nv_bfloat16* wh = blockIdx.y ? g_wh2 : g_wh1;
    __nv_bfloat16* wl = blockIdx.y ? g_wl2 : g_wl1;
    int e = threadIdx.x;
#pragma unroll
    for (int k = 0; k < 3; ++k) {
        __nv_bfloat16 hi, lo;
        split_bf16(w[f * KTOT + e * 3 + k], hi, lo);
        wh[f * KTOT + k * 256 + e] = hi;
        wl[f * KTOT + k * 256 + e] = lo;
    }
}

// ---------------- im2col ----------------
template <int SRC>
__global__ void __launch_bounds__(256) im2col_kernel(const float* __restrict__ x) {
    int warp = threadIdx.x >> 5, lane = threadIdx.x & 31;
    int row = blockIdx.x * 8 + warp;
    int n = row >> 9, l = row & 511;
    int e0 = lane * 8;
    __nv_bfloat16* dh = SRC ? g_xh2 : g_xh1;
    __nv_bfloat16* dl = SRC ? g_xl2 : g_xl1;
#pragma unroll
    for (int k = 0; k < 3; ++k) {
        int sl = l + k - 1;
        uint4 vh = make_uint4(0u, 0u, 0u, 0u), vl = vh;
        if (sl >= 0 && sl < LL) {
            if (SRC == 0) {
                const float* xr = x + ((size_t)(n * LL + sl) * EE + e0);
                uint32_t* ph = reinterpret_cast<uint32_t*>(&vh);
                uint32_t* pl = reinterpret_cast<uint32_t*>(&vl);
#pragma unroll
                for (int q = 0; q < 4; ++q) {
                    __nv_bfloat16 h0, l0, h1, l1;
                    split_bf16(xr[2 * q], h0, l0);
                    split_bf16(xr[2 * q + 1], h1, l1);
                    ph[q] = ((uint32_t)*reinterpret_cast<uint16_t*>(&h1) << 16) |
                            *reinterpret_cast<uint16_t*>(&h0);
                    pl[q] = ((uint32_t)*reinterpret_cast<uint16_t*>(&l1) << 16) |
                            *reinterpret_cast<uint16_t*>(&l0);
                }
            } else {
                size_t off = (size_t)(n * LL + sl) * FF + e0;
                vh = *reinterpret_cast<const uint4*>(g_h1h + off);
                vl = *reinterpret_cast<const uint4*>(g_h1l + off);
            }
        }
        size_t doff = (size_t)row * KTOT + k * 256 + e0;
        *reinterpret_cast<uint4*>(dh + doff) = vh;
        *reinterpret_cast<uint4*>(dl + doff) = vl;
    }
}

// ---------------- build idx map ----------------
__global__ void build_idx_kernel(const int* __restrict__ target) {
    int n = blockIdx.x, t = threadIdx.x;
    __shared__ int s[512];
    int d = target[n * LL + t];
    s[t] = d;
    __syncthreads();
    for (int off = 1; off < 512; off <<= 1) {
        int v = (t >= off) ? s[t - off] : 0;
        __syncthreads();
        s[t] += v;
        __syncthreads();
    }
    int cum = s[t], start = cum - d;
    for (int i = t; i < MM; i += 512) g_idx[n * MM + i] = -1;
    __syncthreads();
    for (int u = start; u < cum; ++u) g_idx[n * MM + u] = t;
}

// ---------------- 3xBF16 HMMA GEMM + fused LN/ReLU (+ fused gather) ----------
// CTA: M=64, N=256.  256 threads, 8 warps (2m x 4n), warp tile 32x64.
// KC=64, 2-stage cp.async; ldmatrix.x4 frags, double-buffered across ksteps.
// SECOND=1 additionally streams 512 gather rows per CTA through the mainloop.
template <int SECOND>
__global__ void __launch_bounds__(256) gemm_ln_kernel(
    const float* __restrict__ bias, const float* __restrict__ gamma,
    const float* __restrict__ beta, const float* __restrict__ lw,
    const float* __restrict__ lbp, float* __restrict__ durout,
    const float* __restrict__ x, float* __restrict__ out)
{
    extern __shared__ char smem[];
    uint32_t sb = smem_u32(smem);
    int tid = threadIdx.x, wid = tid >> 5, lane = tid & 31;
    int m0 = blockIdx.x * 64;
    int wm = wid & 1, wn = wid >> 1;
    int g = lane >> 2, t = lane & 3;
    const __nv_bfloat16* Ah = SECOND ? g_xh2 : g_xh1;
    const __nv_bfloat16* Al = SECOND ? g_xl2 : g_xl1;
    const __nv_bfloat16* Bh = SECOND ? g_wh2 : g_wh1;
    const __nv_bfloat16* Bl = SECOND ? g_wl2 : g_wl1;

    {
        float* pp = reinterpret_cast<float*>(smem + SM_PAR);
        pp[tid] = bias[tid];
        pp[256 + tid] = gamma[tid];
        pp[512 + tid] = beta[tid];
        pp[768 + tid] = SECOND ? lw[tid] : 0.f;
    }

    // ldmatrix lane-address components (within-warp, per-lane constants)
    int a_row = (( (lane >> 3) & 1) << 3) + (lane & 7);      // +0/8 row in m16 tile
    int a_kb  = (lane >> 4) << 4;                            // +0/16 bytes (k0/k8)
    int b_row = ((lane >> 4) << 3) + (lane & 7);             // row within nt-pair (0..15)
    int b_kb  = ((lane >> 3) & 1) << 4;                      // +0/16 bytes

    auto issue_chunk = [&](int c, int buf) {
        uint32_t sa = sb + buf * STAGE;
        uint32_t sbm = sa + ASZ;
        size_t aoff = ((size_t)m0 * KTOT + c * KC) * 2;
        size_t boff = (size_t)c * KC * 2;
        const char* gAh = reinterpret_cast<const char*>(Ah) + aoff;
        const char* gAl = reinterpret_cast<const char*>(Al) + aoff;
        const char* gBh = reinterpret_cast<const char*>(Bh) + boff;
        const char* gBl = reinterpret_cast<const char*>(Bl) + boff;
#pragma unroll
        for (int i = 0; i < 2; ++i) {          // A: 64 rows x 8 segs per plane
            int lin = tid + (i << 8);
            int row = lin >> 3, seg = lin & 7;
            cp16(sa + row * ROWB + seg * 16, gAh + (size_t)row * 1536 + seg * 16);
            cp16(sa + (64 + row) * ROWB + seg * 16, gAl + (size_t)row * 1536 + seg * 16);
        }
#pragma unroll
        for (int i = 0; i < 8; ++i) {          // B: 256 rows x 8 segs, both planes
            int lin = tid + (i << 8);
            int row = lin >> 3, seg = lin & 7;
            cp16(sbm + row * ROWB + seg * 16, gBh + (size_t)row * 1536 + seg * 16);
            cp16(sbm + (256 + row) * ROWB + seg * 16, gBl + (size_t)row * 1536 + seg * 16);
        }
        CP_COMMIT();
    };

    float acc[2][8][4];
#pragma unroll
    for (int mt = 0; mt < 2; ++mt)
#pragma unroll
        for (int nt = 0; nt < 8; ++nt)
#pragma unroll
            for (int q = 0; q < 4; ++q) acc[mt][nt][q] = 0.f;

    // fragment buffers (double-buffered over ksteps)
    uint32_t fAh[2][2][4], fAl[2][2][4];       // [buf][mt][a0..a3]
    uint32_t fBh[2][8][2], fBl[2][8][2];       // [buf][nt][b0,b1]

    auto load_frags = [&](int fb, uint32_t abase, uint32_t bbase, int k0) {
#pragma unroll
        for (int mt = 0; mt < 2; ++mt) {
            uint32_t ra = abase + (wm * 32 + mt * 16 + a_row) * ROWB + k0 * 2 + a_kb;
            ldsm4(fAh[fb][mt], ra);
            ldsm4(fAl[fb][mt], ra + 64 * ROWB);
        }
#pragma unroll
        for (int np = 0; np < 4; ++np) {       // nt pairs {0,1},{2,3},{4,5},{6,7}
            uint32_t rb = bbase + (wn * 64 + np * 16 + b_row) * ROWB + k0 * 2 + b_kb;
            uint32_t r[4];
            ldsm4(r, rb);
            fBh[fb][2 * np][0] = r[0]; fBh[fb][2 * np][1] = r[1];
            fBh[fb][2 * np + 1][0] = r[2]; fBh[fb][2 * np + 1][1] = r[3];
            ldsm4(r, rb + 256 * ROWB);
            fBl[fb][2 * np][0] = r[0]; fBl[fb][2 * np][1] = r[1];
            fBl[fb][2 * np + 1][0] = r[2]; fBl[fb][2 * np + 1][1] = r[3];
        }
    };

    issue_chunk(0, 0);
    for (int c = 0; c < NCHUNK; ++c) {
        int buf = c & 1;
        if (c + 1 < NCHUNK) issue_chunk(c + 1, buf ^ 1);
        // fused gather (SECOND only): overlap DRAM stream with the wait + MMAs
        if (SECOND) {
            int base_r = c * 43;
            int nrows = 512 - base_r;
            if (nrows > 43) nrows = 43;
            if (nrows > 0) {
                int tot = nrows << 6;
                for (int i = tid; i < tot; i += 256) {
                    int grow = blockIdx.x * 512 + base_r + (i >> 6);
                    int n = grow >> 12;
                    int j = g_idx[grow];
                    float4 v = make_float4(0.f, 0.f, 0.f, 0.f);
                    if (j >= 0)
                        v = __ldg(reinterpret_cast<const float4*>(
                                x + (size_t)(n * LL + j) * EE) + (i & 63));
                    reinterpret_cast<float4*>(out + (size_t)grow * EE)[i & 63] = v;
                }
            }
        }
        if (c + 1 < NCHUNK) cp_wait<1>(); else cp_wait<0>();
        __syncthreads();
        uint32_t abase = sb + buf * STAGE;
        uint32_t bbase = abase + ASZ;
        load_frags(0, abase, bbase, 0);
#pragma unroll
        for (int ks = 0; ks < 4; ++ks) {
            int fb = ks & 1;
            if (ks < 3) load_frags(fb ^ 1, abase, bbase, (ks + 1) * 16);
#pragma unroll
            for (int mt = 0; mt < 2; ++mt) {
                uint32_t* ah = fAh[fb][mt];
                uint32_t* al = fAl[fb][mt];
#pragma unroll
                for (int nt = 0; nt < 8; ++nt) {
                    mma_bf16(acc[mt][nt], ah[0], ah[1], ah[2], ah[3],
                             fBh[fb][nt][0], fBh[fb][nt][1]);
                    mma_bf16(acc[mt][nt], ah[0], ah[1], ah[2], ah[3],
                             fBl[fb][nt][0], fBl[fb][nt][1]);
                    mma_bf16(acc[mt][nt], al[0], al[1], al[2], al[3],
                             fBh[fb][nt][0], fBh[fb][nt][1]);
                }
            }
        }
        __syncthreads();
    }

    // ---------------- epilogue ----------------
    float* ot = reinterpret_cast<float*>(smem);   // [64][260] fp32
#pragma unroll
    for (int mt = 0; mt < 2; ++mt)
#pragma unroll
        for (int nt = 0; nt < 8; ++nt) {
            int m = wm * 32 + mt * 16 + g;
            int n = wn * 64 + nt * 8 + 2 * t;
            *reinterpret_cast<float2*>(ot + m * 260 + n) =
                make_float2(acc[mt][nt][0], acc[mt][nt][1]);
            *reinterpret_cast<float2*>(ot + (m + 8) * 260 + n) =
                make_float2(acc[mt][nt][2], acc[mt][nt][3]);
        }
    __syncthreads();

    if (tid < 64) {
        const float* pb = reinterpret_cast<const float*>(smem + SM_PAR);
        const float* pg = pb + 256;
        const float* pe = pb + 512;
        const float* pl = pb + 768;
        const float* rowp = ot + tid * 260;
        float h[256];
        float s = 0.f, ss = 0.f;
#pragma unroll 4
        for (int j = 0; j < 256; j += 4) {
            float4 v4 = *reinterpret_cast<const float4*>(rowp + j);
            h[j]     = v4.x + pb[j];
            h[j + 1] = v4.y + pb[j + 1];
            h[j + 2] = v4.z + pb[j + 2];
            h[j + 3] = v4.w + pb[j + 3];
            s += h[j] + h[j + 1] + h[j + 2] + h[j + 3];
            ss += h[j] * h[j] + h[j + 1] * h[j + 1] +
                  h[j + 2] * h[j + 2] + h[j + 3] * h[j + 3];
        }
        float mu = s * (1.f / 256.f);
        float var = ss * (1.f / 256.f) - mu * mu;
        float rs = rsqrtf(var + 1e-5f);
        int row = m0 + tid;
        if (!SECOND) {
            __nv_bfloat16* dh = g_h1h + (size_t)row * FF;
            __nv_bfloat16* dl = g_h1l + (size_t)row * FF;
#pragma unroll 2
            for (int j = 0; j < 256; j += 8) {
                uint32_t wh[4], wl[4];
#pragma unroll
                for (int q = 0; q < 4; ++q) {
                    float y0 = fmaxf(0.f, (h[j + 2 * q] - mu) * rs * pg[j + 2 * q] + pe[j + 2 * q]);
                    float y1 = fmaxf(0.f, (h[j + 2 * q + 1] - mu) * rs * pg[j + 2 * q + 1] + pe[j + 2 * q + 1]);
                    __nv_bfloat16 h0, l0, h1, l1;
                    split_bf16(y0, h0, l0);
                    split_bf16(y1, h1, l1);
                    wh[q] = ((uint32_t)*reinterpret_cast<uint16_t*>(&h1) << 16) |
                            *reinterpret_cast<uint16_t*>(&h0);
                    wl[q] = ((uint32_t)*reinterpret_cast<uint16_t*>(&l1) << 16) |
                            *reinterpret_cast<uint16_t*>(&l0);
                }
                *reinterpret_cast<uint4*>(dh + j) = make_uint4(wh[0], wh[1], wh[2], wh[3]);
                *reinterpret_cast<uint4*>(dl + j) = make_uint4(wl[0], wl[1], wl[2], wl[3]);
            }
        } else {
            float dacc = 0.f;
#pragma unroll 4
            for (int j = 0; j < 256; ++j) {
                float y = fmaxf(0.f, (h[j] - mu) * rs * pg[j] + pe[j]);
                dacc += y * pl[j];
            }
            durout[row] = fmaxf(0.f, dacc + *lbp);
        }
    }
}

// ---------------- launch ----------------
extern "C" void kernel_launch(void* const* d_in, const int* in_sizes, int n_in,
                              void* d_out, int out_size) {
    const float* x   = (const float*)d_in[0];
    const float* c1w = (const float*)d_in[1];
    const float* c1b = (const float*)d_in[2];
    const float* l1g = (const float*)d_in[3];
    const float* l1b = (const float*)d_in[4];
    const float* c2w = (const float*)d_in[5];
    const float* c2b = (const float*)d_in[6];
    const float* l2g = (const float*)d_in[7];
    const float* l2b = (const float*)d_in[8];
    const float* lw  = (const float*)d_in[9];
    const float* lb  = (const float*)d_in[10];
    const int* target = (const int*)d_in[11];
    float* out = (float*)d_out;

    cudaFuncSetAttribute(gemm_ln_kernel<0>, cudaFuncAttributeMaxDynamicSharedMemorySize, SM_TOTAL);
    cudaFuncSetAttribute(gemm_ln_kernel<1>, cudaFuncAttributeMaxDynamicSharedMemorySize, SM_TOTAL);

    prep_w_kernel<<<dim3(256, 2), 256>>>(c1w, c2w);
    im2col_kernel<0><<<NROWS / 8, 256>>>(x);
    build_idx_kernel<<<16, 512>>>(target);
    gemm_ln_kernel<0><<<128, 256, SM_TOTAL>>>(c1b, l1g, l1b, lw, lb, nullptr, nullptr, nullptr);
    im2col_kernel<1><<<NROWS / 8, 256>>>(nullptr);
    gemm_ln_kernel<1><<<128, 256, SM_TOTAL>>>(c2b, l2g, l2b, lw, lb, out + OUT_ELEMS, x, out);
}

// round 11
// speedup vs baseline: 1.3405x; 1.3405x over previous
#include <cuda_runtime.h>
#include <cuda_bf16.h>
#include <cstdint>

#define NB 16
#define LL 512
#define EE 256
#define FF 256
#define MM 4096
#define OUT_ELEMS (NB * MM * EE)   // 16777216
#define KTOT 768
#define NROWS (NB * LL)            // 8192
#define KC 64                      // K chunk (bf16)
#define NCHUNK (KTOT / KC)         // 12
#define PADK 72                    // padded row length (bf16) -> 144 B
#define ROWB (PADK * 2)            // 144 bytes

// ---------------- scratch (hi/lo bf16 planes for 3xBF16 compensation) --------
__device__ __nv_bfloat16 g_xh1[NROWS * KTOT];
__device__ __nv_bfloat16 g_xl1[NROWS * KTOT];
__device__ __nv_bfloat16 g_xh2[NROWS * KTOT];
__device__ __nv_bfloat16 g_xl2[NROWS * KTOT];
__device__ __nv_bfloat16 g_h1h[NROWS * FF];
__device__ __nv_bfloat16 g_h1l[NROWS * FF];
__device__ __nv_bfloat16 g_wh1[FF * KTOT];
__device__ __nv_bfloat16 g_wl1[FF * KTOT];
__device__ __nv_bfloat16 g_wh2[FF * KTOT];
__device__ __nv_bfloat16 g_wl2[FF * KTOT];
__device__ int           g_idx[NB * MM];

// ---------------- smem layout ----------------
#define ASZ   (128 * ROWB)             // A_hi rows 0-63, A_lo rows 64-127
#define BSZ   (512 * ROWB)             // B_hi rows 0-255, B_lo rows 256-511
#define STAGE (ASZ + BSZ)              // 92160
#define SM_PAR (2 * STAGE)             // 184320
#define SM_TOTAL (SM_PAR + 4096)       // 188416

// ---------------- helpers ----------------
__device__ __forceinline__ uint32_t smem_u32(const void* p) {
    uint32_t a;
    asm("{ .reg .u64 t; cvta.to.shared.u64 t, %1; cvt.u32.u64 %0, t; }" : "=r"(a) : "l"(p));
    return a;
}
__device__ __forceinline__ void cp16(uint32_t dst, const void* src) {
    asm volatile("cp.async.cg.shared.global [%0], [%1], 16;" :: "r"(dst), "l"(src));
}
#define CP_COMMIT() asm volatile("cp.async.commit_group;" ::: "memory")
template <int N>
__device__ __forceinline__ void cp_wait() {
    asm volatile("cp.async.wait_group %0;" :: "n"(N) : "memory");
}
__device__ __forceinline__ void ldsm4(uint32_t* r, uint32_t addr) {
    asm volatile("ldmatrix.sync.aligned.m8n8.x4.shared.b16 {%0,%1,%2,%3}, [%4];"
                 : "=r"(r[0]), "=r"(r[1]), "=r"(r[2]), "=r"(r[3]) : "r"(addr));
}
// NOTE: non-volatile — pure register op, lets ptxas schedule/reorder freely.
__device__ __forceinline__ void mma_bf16(float* d, uint32_t a0, uint32_t a1,
                                         uint32_t a2, uint32_t a3,
                                         uint32_t b0, uint32_t b1) {
    asm("mma.sync.aligned.m16n8k16.row.col.f32.bf16.bf16.f32 "
        "{%0,%1,%2,%3}, {%4,%5,%6,%7}, {%8,%9}, {%0,%1,%2,%3};"
        : "+f"(d[0]), "+f"(d[1]), "+f"(d[2]), "+f"(d[3])
        : "r"(a0), "r"(a1), "r"(a2), "r"(a3), "r"(b0), "r"(b1));
}
__device__ __forceinline__ void split_bf16(float v, __nv_bfloat16& hi, __nv_bfloat16& lo) {
    hi = __float2bfloat16(v);
    lo = __float2bfloat16(v - __bfloat162float(hi));
}

// ---------------- weight prep ----------------
__global__ void prep_w_kernel(const float* __restrict__ w1, const float* __restrict__ w2) {
    int f = blockIdx.x;
    const float* w = blockIdx.y ? w2 : w1;
    __nv_bfloat16* wh = blockIdx.y ? g_wh2 : g_wh1;
    __nv_bfloat16* wl = blockIdx.y ? g_wl2 : g_wl1;
    int e = threadIdx.x;
#pragma unroll
    for (int k = 0; k < 3; ++k) {
        __nv_bfloat16 hi, lo;
        split_bf16(w[f * KTOT + e * 3 + k], hi, lo);
        wh[f * KTOT + k * 256 + e] = hi;
        wl[f * KTOT + k * 256 + e] = lo;
    }
}

// ---------------- im2col ----------------
template <int SRC>
__global__ void __launch_bounds__(256) im2col_kernel(const float* __restrict__ x) {
    int warp = threadIdx.x >> 5, lane = threadIdx.x & 31;
    int row = blockIdx.x * 8 + warp;
    int n = row >> 9, l = row & 511;
    int e0 = lane * 8;
    __nv_bfloat16* dh = SRC ? g_xh2 : g_xh1;
    __nv_bfloat16* dl = SRC ? g_xl2 : g_xl1;
#pragma unroll
    for (int k = 0; k < 3; ++k) {
        int sl = l + k - 1;
        uint4 vh = make_uint4(0u, 0u, 0u, 0u), vl = vh;
        if (sl >= 0 && sl < LL) {
            if (SRC == 0) {
                const float* xr = x + ((size_t)(n * LL + sl) * EE + e0);
                uint32_t* ph = reinterpret_cast<uint32_t*>(&vh);
                uint32_t* pl = reinterpret_cast<uint32_t*>(&vl);
#pragma unroll
                for (int q = 0; q < 4; ++q) {
                    __nv_bfloat16 h0, l0, h1, l1;
                    split_bf16(xr[2 * q], h0, l0);
                    split_bf16(xr[2 * q + 1], h1, l1);
                    ph[q] = ((uint32_t)*reinterpret_cast<uint16_t*>(&h1) << 16) |
                            *reinterpret_cast<uint16_t*>(&h0);
                    pl[q] = ((uint32_t)*reinterpret_cast<uint16_t*>(&l1) << 16) |
                            *reinterpret_cast<uint16_t*>(&l0);
                }
            } else {
                size_t off = (size_t)(n * LL + sl) * FF + e0;
                vh = *reinterpret_cast<const uint4*>(g_h1h + off);
                vl = *reinterpret_cast<const uint4*>(g_h1l + off);
            }
        }
        size_t doff = (size_t)row * KTOT + k * 256 + e0;
        *reinterpret_cast<uint4*>(dh + doff) = vh;
        *reinterpret_cast<uint4*>(dl + doff) = vl;
    }
}

// ---------------- build idx map ----------------
__global__ void build_idx_kernel(const int* __restrict__ target) {
    int n = blockIdx.x, t = threadIdx.x;
    __shared__ int s[512];
    int d = target[n * LL + t];
    s[t] = d;
    __syncthreads();
    for (int off = 1; off < 512; off <<= 1) {
        int v = (t >= off) ? s[t - off] : 0;
        __syncthreads();
        s[t] += v;
        __syncthreads();
    }
    int cum = s[t], start = cum - d;
    for (int i = t; i < MM; i += 512) g_idx[n * MM + i] = -1;
    __syncthreads();
    for (int u = start; u < cum; ++u) g_idx[n * MM + u] = t;
}

// ---------------- gather ----------------
__global__ void gather_kernel(const float* __restrict__ x, float* __restrict__ out) {
    int warp = threadIdx.x >> 5, lane = threadIdx.x & 31;
    int row = blockIdx.x * 8 + warp;
    int n = row >> 12;
    int j = g_idx[row];
    float4 v0 = make_float4(0.f, 0.f, 0.f, 0.f), v1 = v0;
    if (j >= 0) {
        const float4* src = reinterpret_cast<const float4*>(x + (size_t)(n * LL + j) * EE);
        v0 = src[lane * 2];
        v1 = src[lane * 2 + 1];
    }
    float4* dst = reinterpret_cast<float4*>(out + (size_t)row * EE);
    dst[lane * 2] = v0;
    dst[lane * 2 + 1] = v1;
}

// ---------------- 3xBF16 HMMA GEMM + fused LN/ReLU epilogue ------------------
// CTA: M=64, N=256.  256 threads, 8 warps (2m x 4n), warp tile 32x64.
// KC=64, 2-stage cp.async; ldmatrix.x4 frags (single-buffered per kstep).
// MMA order is term-major (hh x8nt, hl x8nt, lh x8nt) so consecutive MMAs hit
// distinct accumulators — no RAW chains.
template <int SECOND>
__global__ void __launch_bounds__(256) gemm_ln_kernel(
    const float* __restrict__ bias, const float* __restrict__ gamma,
    const float* __restrict__ beta, const float* __restrict__ lw,
    const float* __restrict__ lbp, float* __restrict__ durout)
{
    extern __shared__ char smem[];
    uint32_t sb = smem_u32(smem);
    int tid = threadIdx.x, wid = tid >> 5, lane = tid & 31;
    int m0 = blockIdx.x * 64;
    int wm = wid & 1, wn = wid >> 1;
    int g = lane >> 2, t = lane & 3;
    const __nv_bfloat16* Ah = SECOND ? g_xh2 : g_xh1;
    const __nv_bfloat16* Al = SECOND ? g_xl2 : g_xl1;
    const __nv_bfloat16* Bh = SECOND ? g_wh2 : g_wh1;
    const __nv_bfloat16* Bl = SECOND ? g_wl2 : g_wl1;

    {
        float* pp = reinterpret_cast<float*>(smem + SM_PAR);
        pp[tid] = bias[tid];
        pp[256 + tid] = gamma[tid];
        pp[512 + tid] = beta[tid];
        pp[768 + tid] = SECOND ? lw[tid] : 0.f;
    }

    // ldmatrix lane-address components
    int a_row = (((lane >> 3) & 1) << 3) + (lane & 7);
    int a_kb  = (lane >> 4) << 4;
    int b_row = ((lane >> 4) << 3) + (lane & 7);
    int b_kb  = ((lane >> 3) & 1) << 4;

    auto issue_chunk = [&](int c, int buf) {
        uint32_t sa = sb + buf * STAGE;
        uint32_t sbm = sa + ASZ;
        size_t aoff = ((size_t)m0 * KTOT + c * KC) * 2;
        size_t boff = (size_t)c * KC * 2;
        const char* gAh = reinterpret_cast<const char*>(Ah) + aoff;
        const char* gAl = reinterpret_cast<const char*>(Al) + aoff;
        const char* gBh = reinterpret_cast<const char*>(Bh) + boff;
        const char* gBl = reinterpret_cast<const char*>(Bl) + boff;
#pragma unroll
        for (int i = 0; i < 2; ++i) {          // A: 64 rows x 8 segs per plane
            int lin = tid + (i << 8);
            int row = lin >> 3, seg = lin & 7;
            cp16(sa + row * ROWB + seg * 16, gAh + (size_t)row * 1536 + seg * 16);
            cp16(sa + (64 + row) * ROWB + seg * 16, gAl + (size_t)row * 1536 + seg * 16);
        }
#pragma unroll
        for (int i = 0; i < 8; ++i) {          // B: 256 rows x 8 segs, both planes
            int lin = tid + (i << 8);
            int row = lin >> 3, seg = lin & 7;
            cp16(sbm + row * ROWB + seg * 16, gBh + (size_t)row * 1536 + seg * 16);
            cp16(sbm + (256 + row) * ROWB + seg * 16, gBl + (size_t)row * 1536 + seg * 16);
        }
        CP_COMMIT();
    };

    float acc[2][8][4];
#pragma unroll
    for (int mt = 0; mt < 2; ++mt)
#pragma unroll
        for (int nt = 0; nt < 8; ++nt)
#pragma unroll
            for (int q = 0; q < 4; ++q) acc[mt][nt][q] = 0.f;

    issue_chunk(0, 0);
    for (int c = 0; c < NCHUNK; ++c) {
        int buf = c & 1;
        if (c + 1 < NCHUNK) {
            issue_chunk(c + 1, buf ^ 1);
            cp_wait<1>();
        } else {
            cp_wait<0>();
        }
        __syncthreads();
        uint32_t abase = sb + buf * STAGE;
        uint32_t bbase = abase + ASZ;
#pragma unroll
        for (int ks = 0; ks < 4; ++ks) {
            int k0 = ks * 16;
            // fragments (single-buffered per kstep)
            uint32_t fAh[2][4], fAl[2][4];     // [mt][a0..a3]
            uint32_t fBh[8][2], fBl[8][2];     // [nt][b0,b1]
#pragma unroll
            for (int mt = 0; mt < 2; ++mt) {
                uint32_t ra = abase + (wm * 32 + mt * 16 + a_row) * ROWB + k0 * 2 + a_kb;
                ldsm4(fAh[mt], ra);
                ldsm4(fAl[mt], ra + 64 * ROWB);
            }
#pragma unroll
            for (int np = 0; np < 4; ++np) {
                uint32_t rb = bbase + (wn * 64 + np * 16 + b_row) * ROWB + k0 * 2 + b_kb;
                uint32_t r[4];
                ldsm4(r, rb);
                fBh[2 * np][0] = r[0]; fBh[2 * np][1] = r[1];
                fBh[2 * np + 1][0] = r[2]; fBh[2 * np + 1][1] = r[3];
                ldsm4(r, rb + 256 * ROWB);
                fBl[2 * np][0] = r[0]; fBl[2 * np][1] = r[1];
                fBl[2 * np + 1][0] = r[2]; fBl[2 * np + 1][1] = r[3];
            }
            // term-major MMA order: consecutive MMAs use distinct accumulators
#pragma unroll
            for (int mt = 0; mt < 2; ++mt) {
#pragma unroll
                for (int nt = 0; nt < 8; ++nt)
                    mma_bf16(acc[mt][nt], fAh[mt][0], fAh[mt][1], fAh[mt][2], fAh[mt][3],
                             fBh[nt][0], fBh[nt][1]);
#pragma unroll
                for (int nt = 0; nt < 8; ++nt)
                    mma_bf16(acc[mt][nt], fAh[mt][0], fAh[mt][1], fAh[mt][2], fAh[mt][3],
                             fBl[nt][0], fBl[nt][1]);
#pragma unroll
                for (int nt = 0; nt < 8; ++nt)
                    mma_bf16(acc[mt][nt], fAl[mt][0], fAl[mt][1], fAl[mt][2], fAl[mt][3],
                             fBh[nt][0], fBh[nt][1]);
            }
        }
        __syncthreads();
    }

    // ---------------- epilogue ----------------
    float* ot = reinterpret_cast<float*>(smem);   // [64][260] fp32
#pragma unroll
    for (int mt = 0; mt < 2; ++mt)
#pragma unroll
        for (int nt = 0; nt < 8; ++nt) {
            int m = wm * 32 + mt * 16 + g;
            int n = wn * 64 + nt * 8 + 2 * t;
            *reinterpret_cast<float2*>(ot + m * 260 + n) =
                make_float2(acc[mt][nt][0], acc[mt][nt][1]);
            *reinterpret_cast<float2*>(ot + (m + 8) * 260 + n) =
                make_float2(acc[mt][nt][2], acc[mt][nt][3]);
        }
    __syncthreads();

    if (tid < 64) {
        const float* pb = reinterpret_cast<const float*>(smem + SM_PAR);
        const float* pg = pb + 256;
        const float* pe = pb + 512;
        const float* pl = pb + 768;
        const float* rowp = ot + tid * 260;
        float h[256];
        float s = 0.f, ss = 0.f;
#pragma unroll 4
        for (int j = 0; j < 256; j += 4) {
            float4 v4 = *reinterpret_cast<const float4*>(rowp + j);
            h[j]     = v4.x + pb[j];
            h[j + 1] = v4.y + pb[j + 1];
            h[j + 2] = v4.z + pb[j + 2];
            h[j + 3] = v4.w + pb[j + 3];
            s += h[j] + h[j + 1] + h[j + 2] + h[j + 3];
            ss += h[j] * h[j] + h[j + 1] * h[j + 1] +
                  h[j + 2] * h[j + 2] + h[j + 3] * h[j + 3];
        }
        float mu = s * (1.f / 256.f);
        float var = ss * (1.f / 256.f) - mu * mu;
        float rs = rsqrtf(var + 1e-5f);
        int row = m0 + tid;
        if (!SECOND) {
            __nv_bfloat16* dh = g_h1h + (size_t)row * FF;
            __nv_bfloat16* dl = g_h1l + (size_t)row * FF;
#pragma unroll 2
            for (int j = 0; j < 256; j += 8) {
                uint32_t wh[4], wl[4];
#pragma unroll
                for (int q = 0; q < 4; ++q) {
                    float y0 = fmaxf(0.f, (h[j + 2 * q] - mu) * rs * pg[j + 2 * q] + pe[j + 2 * q]);
                    float y1 = fmaxf(0.f, (h[j + 2 * q + 1] - mu) * rs * pg[j + 2 * q + 1] + pe[j + 2 * q + 1]);
                    __nv_bfloat16 h0, l0, h1, l1;
                    split_bf16(y0, h0, l0);
                    split_bf16(y1, h1, l1);
                    wh[q] = ((uint32_t)*reinterpret_cast<uint16_t*>(&h1) << 16) |
                            *reinterpret_cast<uint16_t*>(&h0);
                    wl[q] = ((uint32_t)*reinterpret_cast<uint16_t*>(&l1) << 16) |
                            *reinterpret_cast<uint16_t*>(&l0);
                }
                *reinterpret_cast<uint4*>(dh + j) = make_uint4(wh[0], wh[1], wh[2], wh[3]);
                *reinterpret_cast<uint4*>(dl + j) = make_uint4(wl[0], wl[1], wl[2], wl[3]);
            }
        } else {
            float dacc = 0.f;
#pragma unroll 4
            for (int j = 0; j < 256; ++j) {
                float y = fmaxf(0.f, (h[j] - mu) * rs * pg[j] + pe[j]);
                dacc += y * pl[j];
            }
            durout[row] = fmaxf(0.f, dacc + *lbp);
        }
    }
}

// ---------------- launch ----------------
extern "C" void kernel_launch(void* const* d_in, const int* in_sizes, int n_in,
                              void* d_out, int out_size) {
    const float* x   = (const float*)d_in[0];
    const float* c1w = (const float*)d_in[1];
    const float* c1b = (const float*)d_in[2];
    const float* l1g = (const float*)d_in[3];
    const float* l1b = (const float*)d_in[4];
    const float* c2w = (const float*)d_in[5];
    const float* c2b = (const float*)d_in[6];
    const float* l2g = (const float*)d_in[7];
    const float* l2b = (const float*)d_in[8];
    const float* lw  = (const float*)d_in[9];
    const float* lb  = (const float*)d_in[10];
    const int* target = (const int*)d_in[11];
    float* out = (float*)d_out;

    cudaFuncSetAttribute(gemm_ln_kernel<0>, cudaFuncAttributeMaxDynamicSharedMemorySize, SM_TOTAL);
    cudaFuncSetAttribute(gemm_ln_kernel<1>, cudaFuncAttributeMaxDynamicSharedMemorySize, SM_TOTAL);

    prep_w_kernel<<<dim3(256, 2), 256>>>(c1w, c2w);
    im2col_kernel<0><<<NROWS / 8, 256>>>(x);
    build_idx_kernel<<<16, 512>>>(target);
    gemm_ln_kernel<0><<<128, 256, SM_TOTAL>>>(c1b, l1g, l1b, lw, lb, nullptr);
    im2col_kernel<1><<<NROWS / 8, 256>>>(nullptr);
    gemm_ln_kernel<1><<<128, 256, SM_TOTAL>>>(c2b, l2g, l2b, lw, lb, out + OUT_ELEMS);
    gather_kernel<<<NB * MM / 8, 256>>>(x, out);
}

// round 12
// speedup vs baseline: 1.4343x; 1.0700x over previous
#include <cuda_runtime.h>
#include <cuda_bf16.h>
#include <cstdint>

#define NB 16
#define LL 512
#define EE 256
#define FF 256
#define MM 4096
#define OUT_ELEMS (NB * MM * EE)   // 16777216
#define KTOT 768
#define NROWS (NB * LL)            // 8192
#define KC 64                      // K chunk (bf16)
#define NCHUNK (KTOT / KC)         // 12
#define PADK 72                    // padded row length (bf16) -> 144 B
#define ROWB (PADK * 2)            // 144 bytes
#define GROWS_HALF (NB * MM / 2)   // 32768 gather rows per gemm kernel

// ---------------- scratch (hi/lo bf16 planes for 3xBF16 compensation) --------
__device__ __nv_bfloat16 g_xh1[NROWS * KTOT];
__device__ __nv_bfloat16 g_xl1[NROWS * KTOT];
__device__ __nv_bfloat16 g_xh2[NROWS * KTOT];  // halo slots stay zero-init
__device__ __nv_bfloat16 g_xl2[NROWS * KTOT];
__device__ __nv_bfloat16 g_wh1[FF * KTOT];
__device__ __nv_bfloat16 g_wl1[FF * KTOT];
__device__ __nv_bfloat16 g_wh2[FF * KTOT];
__device__ __nv_bfloat16 g_wl2[FF * KTOT];
__device__ int           g_idx[NB * MM];

// ---------------- smem layout ----------------
#define ASZ   (128 * ROWB)             // A_hi rows 0-63, A_lo rows 64-127
#define BSZ   (512 * ROWB)             // B_hi rows 0-255, B_lo rows 256-511
#define STAGE (ASZ + BSZ)              // 92160
#define SM_PAR (2 * STAGE)             // 184320
#define SM_TOTAL (SM_PAR + 4096)       // 188416

// ---------------- helpers ----------------
__device__ __forceinline__ uint32_t smem_u32(const void* p) {
    uint32_t a;
    asm("{ .reg .u64 t; cvta.to.shared.u64 t, %1; cvt.u32.u64 %0, t; }" : "=r"(a) : "l"(p));
    return a;
}
__device__ __forceinline__ void cp16(uint32_t dst, const void* src) {
    asm volatile("cp.async.cg.shared.global [%0], [%1], 16;" :: "r"(dst), "l"(src));
}
#define CP_COMMIT() asm volatile("cp.async.commit_group;" ::: "memory")
template <int N>
__device__ __forceinline__ void cp_wait() {
    asm volatile("cp.async.wait_group %0;" :: "n"(N) : "memory");
}
// named barrier: GEMM warp group only (256 threads); gather warps never arrive
#define BARG() asm volatile("bar.sync 1, 256;" ::: "memory")
__device__ __forceinline__ void ldsm4(uint32_t* r, uint32_t addr) {
    asm volatile("ldmatrix.sync.aligned.m8n8.x4.shared.b16 {%0,%1,%2,%3}, [%4];"
                 : "=r"(r[0]), "=r"(r[1]), "=r"(r[2]), "=r"(r[3]) : "r"(addr));
}
__device__ __forceinline__ void mma_bf16(float* d, uint32_t a0, uint32_t a1,
                                         uint32_t a2, uint32_t a3,
                                         uint32_t b0, uint32_t b1) {
    asm("mma.sync.aligned.m16n8k16.row.col.f32.bf16.bf16.f32 "
        "{%0,%1,%2,%3}, {%4,%5,%6,%7}, {%8,%9}, {%0,%1,%2,%3};"
        : "+f"(d[0]), "+f"(d[1]), "+f"(d[2]), "+f"(d[3])
        : "r"(a0), "r"(a1), "r"(a2), "r"(a3), "r"(b0), "r"(b1));
}
__device__ __forceinline__ void split_bf16(float v, __nv_bfloat16& hi, __nv_bfloat16& lo) {
    hi = __float2bfloat16(v);
    lo = __float2bfloat16(v - __bfloat162float(hi));
}

// ---------------- weight prep ----------------
__global__ void prep_w_kernel(const float* __restrict__ w1, const float* __restrict__ w2) {
    int f = blockIdx.x;
    const float* w = blockIdx.y ? w2 : w1;
    __nv_bfloat16* wh = blockIdx.y ? g_wh2 : g_wh1;
    __nv_bfloat16* wl = blockIdx.y ? g_wl2 : g_wl1;
    int e = threadIdx.x;
#pragma unroll
    for (int k = 0; k < 3; ++k) {
        __nv_bfloat16 hi, lo;
        split_bf16(w[f * KTOT + e * 3 + k], hi, lo);
        wh[f * KTOT + k * 256 + e] = hi;
        wl[f * KTOT + k * 256 + e] = lo;
    }
}

// ---------------- im2col of x (fp32 -> hi/lo planes) ----------------
__global__ void __launch_bounds__(256) im2col_kernel(const float* __restrict__ x) {
    int warp = threadIdx.x >> 5, lane = threadIdx.x & 31;
    int row = blockIdx.x * 8 + warp;
    int n = row >> 9, l = row & 511;
    int e0 = lane * 8;
#pragma unroll
    for (int k = 0; k < 3; ++k) {
        int sl = l + k - 1;
        uint4 vh = make_uint4(0u, 0u, 0u, 0u), vl = vh;
        if (sl >= 0 && sl < LL) {
            const float* xr = x + ((size_t)(n * LL + sl) * EE + e0);
            uint32_t* ph = reinterpret_cast<uint32_t*>(&vh);
            uint32_t* pl = reinterpret_cast<uint32_t*>(&vl);
#pragma unroll
            for (int q = 0; q < 4; ++q) {
                __nv_bfloat16 h0, l0, h1, l1;
                split_bf16(xr[2 * q], h0, l0);
                split_bf16(xr[2 * q + 1], h1, l1);
                ph[q] = ((uint32_t)*reinterpret_cast<uint16_t*>(&h1) << 16) |
                        *reinterpret_cast<uint16_t*>(&h0);
                pl[q] = ((uint32_t)*reinterpret_cast<uint16_t*>(&l1) << 16) |
                        *reinterpret_cast<uint16_t*>(&l0);
            }
        }
        size_t doff = (size_t)row * KTOT + k * 256 + e0;
        *reinterpret_cast<uint4*>(g_xh1 + doff) = vh;
        *reinterpret_cast<uint4*>(g_xl1 + doff) = vl;
    }
}

// ---------------- build idx map ----------------
__global__ void build_idx_kernel(const int* __restrict__ target) {
    int n = blockIdx.x, t = threadIdx.x;
    __shared__ int s[512];
    int d = target[n * LL + t];
    s[t] = d;
    __syncthreads();
    for (int off = 1; off < 512; off <<= 1) {
        int v = (t >= off) ? s[t - off] : 0;
        __syncthreads();
        s[t] += v;
        __syncthreads();
    }
    int cum = s[t], start = cum - d;
    for (int i = t; i < MM; i += 512) g_idx[n * MM + i] = -1;
    __syncthreads();
    for (int u = start; u < cum; ++u) g_idx[n * MM + u] = t;
}

// ---------------- 3xBF16 HMMA GEMM + fused LN/ReLU + warp-specialized gather -
// 384 threads: warps 0-7 = GEMM (named barrier 1), warps 8-11 = gather half.
// SECOND=0: epilogue scatters LN output into g_x2's 3 k-slots (fused im2col).
// SECOND=1: epilogue computes dur_out.
template <int SECOND>
__global__ void __launch_bounds__(384) gemm_ln_kernel(
    const float* __restrict__ bias, const float* __restrict__ gamma,
    const float* __restrict__ beta, const float* __restrict__ lw,
    const float* __restrict__ lbp, float* __restrict__ durout,
    const float* __restrict__ x, float* __restrict__ out)
{
    extern __shared__ char smem[];
    uint32_t sb = smem_u32(smem);
    int tid = threadIdx.x;

    if (tid >= 256) {
        // ---------------- gather warps (fully decoupled) ----------------
        int gt = tid - 256;                       // 0..127
        int w = gt >> 5, lane = gt & 31;
        int rbase = SECOND * GROWS_HALF + blockIdx.x * 256 + w * 64;
        const float4 zero = make_float4(0.f, 0.f, 0.f, 0.f);
        for (int rr = 0; rr < 64; rr += 4) {
            int js[4];
#pragma unroll
            for (int q = 0; q < 4; ++q) js[q] = g_idx[rbase + rr + q];
            float4 v[8];
#pragma unroll
            for (int q = 0; q < 4; ++q) {
                int grow = rbase + rr + q;
                if (js[q] >= 0) {
                    const float4* src = reinterpret_cast<const float4*>(
                        x + (size_t)((grow >> 12) * LL + js[q]) * EE);
                    v[2 * q]     = __ldg(src + lane * 2);
                    v[2 * q + 1] = __ldg(src + lane * 2 + 1);
                } else {
                    v[2 * q] = zero;
                    v[2 * q + 1] = zero;
                }
            }
#pragma unroll
            for (int q = 0; q < 4; ++q) {
                float4* dst = reinterpret_cast<float4*>(
                    out + (size_t)(rbase + rr + q) * EE);
                dst[lane * 2]     = v[2 * q];
                dst[lane * 2 + 1] = v[2 * q + 1];
            }
        }
        return;
    }

    // ---------------- GEMM warp group (tid < 256) ----------------
    int wid = tid >> 5, lane = tid & 31;
    int m0 = blockIdx.x * 64;
    int wm = wid & 1, wn = wid >> 1;
    int g = lane >> 2, t = lane & 3;
    const __nv_bfloat16* Ah = SECOND ? g_xh2 : g_xh1;
    const __nv_bfloat16* Al = SECOND ? g_xl2 : g_xl1;
    const __nv_bfloat16* Bh = SECOND ? g_wh2 : g_wh1;
    const __nv_bfloat16* Bl = SECOND ? g_wl2 : g_wl1;

    {
        float* pp = reinterpret_cast<float*>(smem + SM_PAR);
        pp[tid] = bias[tid];
        pp[256 + tid] = gamma[tid];
        pp[512 + tid] = beta[tid];
        pp[768 + tid] = SECOND ? lw[tid] : 0.f;
    }

    int a_row = (((lane >> 3) & 1) << 3) + (lane & 7);
    int a_kb  = (lane >> 4) << 4;
    int b_row = ((lane >> 4) << 3) + (lane & 7);
    int b_kb  = ((lane >> 3) & 1) << 4;

    auto issue_chunk = [&](int c, int buf) {
        uint32_t sa = sb + buf * STAGE;
        uint32_t sbm = sa + ASZ;
        size_t aoff = ((size_t)m0 * KTOT + c * KC) * 2;
        size_t boff = (size_t)c * KC * 2;
        const char* gAh = reinterpret_cast<const char*>(Ah) + aoff;
        const char* gAl = reinterpret_cast<const char*>(Al) + aoff;
        const char* gBh = reinterpret_cast<const char*>(Bh) + boff;
        const char* gBl = reinterpret_cast<const char*>(Bl) + boff;
#pragma unroll
        for (int i = 0; i < 2; ++i) {          // A: 64 rows x 8 segs per plane
            int lin = tid + (i << 8);
            int row = lin >> 3, seg = lin & 7;
            cp16(sa + row * ROWB + seg * 16, gAh + (size_t)row * 1536 + seg * 16);
            cp16(sa + (64 + row) * ROWB + seg * 16, gAl + (size_t)row * 1536 + seg * 16);
        }
#pragma unroll
        for (int i = 0; i < 8; ++i) {          // B: 256 rows x 8 segs, both planes
            int lin = tid + (i << 8);
            int row = lin >> 3, seg = lin & 7;
            cp16(sbm + row * ROWB + seg * 16, gBh + (size_t)row * 1536 + seg * 16);
            cp16(sbm + (256 + row) * ROWB + seg * 16, gBl + (size_t)row * 1536 + seg * 16);
        }
        CP_COMMIT();
    };

    float acc[2][8][4];
#pragma unroll
    for (int mt = 0; mt < 2; ++mt)
#pragma unroll
        for (int nt = 0; nt < 8; ++nt)
#pragma unroll
            for (int q = 0; q < 4; ++q) acc[mt][nt][q] = 0.f;

    issue_chunk(0, 0);
    for (int c = 0; c < NCHUNK; ++c) {
        int buf = c & 1;
        if (c + 1 < NCHUNK) {
            issue_chunk(c + 1, buf ^ 1);
            cp_wait<1>();
        } else {
            cp_wait<0>();
        }
        BARG();
        uint32_t abase = sb + buf * STAGE;
        uint32_t bbase = abase + ASZ;
#pragma unroll
        for (int ks = 0; ks < 4; ++ks) {
            int k0 = ks * 16;
            uint32_t fAh[2][4], fAl[2][4];
            uint32_t fBh[8][2], fBl[8][2];
#pragma unroll
            for (int mt = 0; mt < 2; ++mt) {
                uint32_t ra = abase + (wm * 32 + mt * 16 + a_row) * ROWB + k0 * 2 + a_kb;
                ldsm4(fAh[mt], ra);
                ldsm4(fAl[mt], ra + 64 * ROWB);
            }
#pragma unroll
            for (int np = 0; np < 4; ++np) {
                uint32_t rb = bbase + (wn * 64 + np * 16 + b_row) * ROWB + k0 * 2 + b_kb;
                uint32_t r[4];
                ldsm4(r, rb);
                fBh[2 * np][0] = r[0]; fBh[2 * np][1] = r[1];
                fBh[2 * np + 1][0] = r[2]; fBh[2 * np + 1][1] = r[3];
                ldsm4(r, rb + 256 * ROWB);
                fBl[2 * np][0] = r[0]; fBl[2 * np][1] = r[1];
                fBl[2 * np + 1][0] = r[2]; fBl[2 * np + 1][1] = r[3];
            }
#pragma unroll
            for (int mt = 0; mt < 2; ++mt) {
#pragma unroll
                for (int nt = 0; nt < 8; ++nt)
                    mma_bf16(acc[mt][nt], fAh[mt][0], fAh[mt][1], fAh[mt][2], fAh[mt][3],
                             fBh[nt][0], fBh[nt][1]);
#pragma unroll
                for (int nt = 0; nt < 8; ++nt)
                    mma_bf16(acc[mt][nt], fAh[mt][0], fAh[mt][1], fAh[mt][2], fAh[mt][3],
                             fBl[nt][0], fBl[nt][1]);
#pragma unroll
                for (int nt = 0; nt < 8; ++nt)
                    mma_bf16(acc[mt][nt], fAl[mt][0], fAl[mt][1], fAl[mt][2], fAl[mt][3],
                             fBh[nt][0], fBh[nt][1]);
            }
        }
        BARG();
    }

    // ---------------- epilogue ----------------
    float* ot = reinterpret_cast<float*>(smem);   // [64][260] fp32, reuses stage 0
#pragma unroll
    for (int mt = 0; mt < 2; ++mt)
#pragma unroll
        for (int nt = 0; nt < 8; ++nt) {
            int m = wm * 32 + mt * 16 + g;
            int n = wn * 64 + nt * 8 + 2 * t;
            *reinterpret_cast<float2*>(ot + m * 260 + n) =
                make_float2(acc[mt][nt][0], acc[mt][nt][1]);
            *reinterpret_cast<float2*>(ot + (m + 8) * 260 + n) =
                make_float2(acc[mt][nt][2], acc[mt][nt][3]);
        }
    BARG();

    if (tid < 64) {
        const float* pb = reinterpret_cast<const float*>(smem + SM_PAR);
        const float* pg = pb + 256;
        const float* pe = pb + 512;
        const float* pl = pb + 768;
        const float* rowp = ot + tid * 260;
        float h[256];
        float s = 0.f, ss = 0.f;
#pragma unroll 4
        for (int j = 0; j < 256; j += 4) {
            float4 v4 = *reinterpret_cast<const float4*>(rowp + j);
            h[j]     = v4.x + pb[j];
            h[j + 1] = v4.y + pb[j + 1];
            h[j + 2] = v4.z + pb[j + 2];
            h[j + 3] = v4.w + pb[j + 3];
            s += h[j] + h[j + 1] + h[j + 2] + h[j + 3];
            ss += h[j] * h[j] + h[j + 1] * h[j + 1] +
                  h[j + 2] * h[j + 2] + h[j + 3] * h[j + 3];
        }
        float mu = s * (1.f / 256.f);
        float var = ss * (1.f / 256.f) - mu * mu;
        float rs = rsqrtf(var + 1e-5f);
        int row = m0 + tid;
        if (!SECOND) {
            // fused im2col: scatter LN output (hi/lo) into g_x2's 3 k-slots
            int l = row & 511;
#pragma unroll 2
            for (int j = 0; j < 256; j += 8) {
                uint32_t wh[4], wl[4];
#pragma unroll
                for (int q = 0; q < 4; ++q) {
                    float y0 = fmaxf(0.f, (h[j + 2 * q] - mu) * rs * pg[j + 2 * q] + pe[j + 2 * q]);
                    float y1 = fmaxf(0.f, (h[j + 2 * q + 1] - mu) * rs * pg[j + 2 * q + 1] + pe[j + 2 * q + 1]);
                    __nv_bfloat16 h0, l0, h1, l1;
                    split_bf16(y0, h0, l0);
                    split_bf16(y1, h1, l1);
                    wh[q] = ((uint32_t)*reinterpret_cast<uint16_t*>(&h1) << 16) |
                            *reinterpret_cast<uint16_t*>(&h0);
                    wl[q] = ((uint32_t)*reinterpret_cast<uint16_t*>(&l1) << 16) |
                            *reinterpret_cast<uint16_t*>(&l0);
                }
                uint4 vh = make_uint4(wh[0], wh[1], wh[2], wh[3]);
                uint4 vl = make_uint4(wl[0], wl[1], wl[2], wl[3]);
                // k=1 slot at row
                *reinterpret_cast<uint4*>(g_xh2 + (size_t)row * KTOT + 256 + j) = vh;
                *reinterpret_cast<uint4*>(g_xl2 + (size_t)row * KTOT + 256 + j) = vl;
                // k=0 slot at row+1
                if (l < 511) {
                    *reinterpret_cast<uint4*>(g_xh2 + (size_t)(row + 1) * KTOT + j) = vh;
                    *reinterpret_cast<uint4*>(g_xl2 + (size_t)(row + 1) * KTOT + j) = vl;
                }
                // k=2 slot at row-1
                if (l > 0) {
                    *reinterpret_cast<uint4*>(g_xh2 + (size_t)(row - 1) * KTOT + 512 + j) = vh;
                    *reinterpret_cast<uint4*>(g_xl2 + (size_t)(row - 1) * KTOT + 512 + j) = vl;
                }
            }
        } else {
            float dacc = 0.f;
#pragma unroll 4
            for (int j = 0; j < 256; ++j) {
                float y = fmaxf(0.f, (h[j] - mu) * rs * pg[j] + pe[j]);
                dacc += y * pl[j];
            }
            durout[row] = fmaxf(0.f, dacc + *lbp);
        }
    }
}

// ---------------- launch ----------------
extern "C" void kernel_launch(void* const* d_in, const int* in_sizes, int n_in,
                              void* d_out, int out_size) {
    const float* x   = (const float*)d_in[0];
    const float* c1w = (const float*)d_in[1];
    const float* c1b = (const float*)d_in[2];
    const float* l1g = (const float*)d_in[3];
    const float* l1b = (const float*)d_in[4];
    const float* c2w = (const float*)d_in[5];
    const float* c2b = (const float*)d_in[6];
    const float* l2g = (const float*)d_in[7];
    const float* l2b = (const float*)d_in[8];
    const float* lw  = (const float*)d_in[9];
    const float* lb  = (const float*)d_in[10];
    const int* target = (const int*)d_in[11];
    float* out = (float*)d_out;

    cudaFuncSetAttribute(gemm_ln_kernel<0>, cudaFuncAttributeMaxDynamicSharedMemorySize, SM_TOTAL);
    cudaFuncSetAttribute(gemm_ln_kernel<1>, cudaFuncAttributeMaxDynamicSharedMemorySize, SM_TOTAL);

    prep_w_kernel<<<dim3(256, 2), 256>>>(c1w, c2w);
    im2col_kernel<<<NROWS / 8, 256>>>(x);
    build_idx_kernel<<<16, 512>>>(target);
    gemm_ln_kernel<0><<<128, 384, SM_TOTAL>>>(c1b, l1g, l1b, lw, lb, nullptr, x, out);
    gemm_ln_kernel<1><<<128, 384, SM_TOTAL>>>(c2b, l2g, l2b, lw, lb, out + OUT_ELEMS, x, out);
}

// round 14
// speedup vs baseline: 1.5107x; 1.0533x over previous
#include <cuda_runtime.h>
#include <cuda_bf16.h>
#include <cstdint>

#define NB 16
#define LL 512
#define EE 256
#define FF 256
#define MM 4096
#define OUT_ELEMS (NB * MM * EE)   // 16777216
#define KTOT 768
#define NROWS (NB * LL)            // 8192
#define KC 64                      // K chunk (bf16)
#define NCHUNK (KTOT / KC)         // 12
#define PADK 72                    // padded row length (bf16) -> 144 B
#define ROWB (PADK * 2)            // 144 bytes
#define GROWS_HALF (NB * MM / 2)   // 32768 gather rows per gemm kernel

// ---------------- scratch (hi/lo bf16 planes for 3xBF16 compensation) --------
__device__ __nv_bfloat16 g_xh1[NROWS * KTOT];
__device__ __nv_bfloat16 g_xl1[NROWS * KTOT];
__device__ __nv_bfloat16 g_xh2[NROWS * KTOT];  // halo slots stay zero-init
__device__ __nv_bfloat16 g_xl2[NROWS * KTOT];
__device__ __nv_bfloat16 g_wh1[FF * KTOT];
__device__ __nv_bfloat16 g_wl1[FF * KTOT];
__device__ __nv_bfloat16 g_wh2[FF * KTOT];
__device__ __nv_bfloat16 g_wl2[FF * KTOT];
__device__ int           g_idx[NB * MM];

// ---------------- smem layout ----------------
#define ASZ   (128 * ROWB)             // A_hi rows 0-63, A_lo rows 64-127
#define BSZ   (512 * ROWB)             // B_hi rows 0-255, B_lo rows 256-511
#define STAGE (ASZ + BSZ)              // 92160
#define SM_PAR (2 * STAGE)             // 184320: bias|gamma|beta|lw (4 KB)
#define SM_MU  (SM_PAR + 4096)         // 64 x float2 (mu, rs)
#define SM_TOTAL (SM_MU + 512)         // 188928

// ---------------- helpers ----------------
__device__ __forceinline__ uint32_t smem_u32(const void* p) {
    uint32_t a;
    asm("{ .reg .u64 t; cvta.to.shared.u64 t, %1; cvt.u32.u64 %0, t; }" : "=r"(a) : "l"(p));
    return a;
}
__device__ __forceinline__ void cp16(uint32_t dst, const void* src) {
    asm volatile("cp.async.cg.shared.global [%0], [%1], 16;" :: "r"(dst), "l"(src));
}
#define CP_COMMIT() asm volatile("cp.async.commit_group;" ::: "memory")
template <int N>
__device__ __forceinline__ void cp_wait() {
    asm volatile("cp.async.wait_group %0;" :: "n"(N) : "memory");
}
// named barrier: GEMM warp group only (256 threads); gather warps never arrive
#define BARG() asm volatile("bar.sync 1, 256;" ::: "memory")
__device__ __forceinline__ void ldsm4(uint32_t* r, uint32_t addr) {
    asm volatile("ldmatrix.sync.aligned.m8n8.x4.shared.b16 {%0,%1,%2,%3}, [%4];"
                 : "=r"(r[0]), "=r"(r[1]), "=r"(r[2]), "=r"(r[3]) : "r"(addr));
}
__device__ __forceinline__ void mma_bf16(float* d, uint32_t a0, uint32_t a1,
                                         uint32_t a2, uint32_t a3,
                                         uint32_t b0, uint32_t b1) {
    asm("mma.sync.aligned.m16n8k16.row.col.f32.bf16.bf16.f32 "
        "{%0,%1,%2,%3}, {%4,%5,%6,%7}, {%8,%9}, {%0,%1,%2,%3};"
        : "+f"(d[0]), "+f"(d[1]), "+f"(d[2]), "+f"(d[3])
        : "r"(a0), "r"(a1), "r"(a2), "r"(a3), "r"(b0), "r"(b1));
}
__device__ __forceinline__ void split_bf16(float v, __nv_bfloat16& hi, __nv_bfloat16& lo) {
    hi = __float2bfloat16(v);
    lo = __float2bfloat16(v - __bfloat162float(hi));
}

// ---------------- weight prep ----------------
__global__ void prep_w_kernel(const float* __restrict__ w1, const float* __restrict__ w2) {
    int f = blockIdx.x;
    const float* w = blockIdx.y ? w2 : w1;
    __nv_bfloat16* wh = blockIdx.y ? g_wh2 : g_wh1;
    __nv_bfloat16* wl = blockIdx.y ? g_wl2 : g_wl1;
    int e = threadIdx.x;
#pragma unroll
    for (int k = 0; k < 3; ++k) {
        __nv_bfloat16 hi, lo;
        split_bf16(w[f * KTOT + e * 3 + k], hi, lo);
        wh[f * KTOT + k * 256 + e] = hi;
        wl[f * KTOT + k * 256 + e] = lo;
    }
}

// ---------------- im2col of x (fp32 -> hi/lo planes) ----------------
__global__ void __launch_bounds__(256) im2col_kernel(const float* __restrict__ x) {
    int warp = threadIdx.x >> 5, lane = threadIdx.x & 31;
    int row = blockIdx.x * 8 + warp;
    int n = row >> 9, l = row & 511;
    int e0 = lane * 8;
#pragma unroll
    for (int k = 0; k < 3; ++k) {
        int sl = l + k - 1;
        uint4 vh = make_uint4(0u, 0u, 0u, 0u), vl = vh;
        if (sl >= 0 && sl < LL) {
            const float* xr = x + ((size_t)(n * LL + sl) * EE + e0);
            uint32_t* ph = reinterpret_cast<uint32_t*>(&vh);
            uint32_t* pl = reinterpret_cast<uint32_t*>(&vl);
#pragma unroll
            for (int q = 0; q < 4; ++q) {
                __nv_bfloat16 h0, l0, h1, l1;
                split_bf16(xr[2 * q], h0, l0);
                split_bf16(xr[2 * q + 1], h1, l1);
                ph[q] = ((uint32_t)*reinterpret_cast<uint16_t*>(&h1) << 16) |
                        *reinterpret_cast<uint16_t*>(&h0);
                pl[q] = ((uint32_t)*reinterpret_cast<uint16_t*>(&l1) << 16) |
                        *reinterpret_cast<uint16_t*>(&l0);
            }
        }
        size_t doff = (size_t)row * KTOT + k * 256 + e0;
        *reinterpret_cast<uint4*>(g_xh1 + doff) = vh;
        *reinterpret_cast<uint4*>(g_xl1 + doff) = vl;
    }
}

// ---------------- build idx map ----------------
__global__ void build_idx_kernel(const int* __restrict__ target) {
    int n = blockIdx.x, t = threadIdx.x;
    __shared__ int s[512];
    int d = target[n * LL + t];
    s[t] = d;
    __syncthreads();
    for (int off = 1; off < 512; off <<= 1) {
        int v = (t >= off) ? s[t - off] : 0;
        __syncthreads();
        s[t] += v;
        __syncthreads();
    }
    int cum = s[t], start = cum - d;
    for (int i = t; i < MM; i += 512) g_idx[n * MM + i] = -1;
    __syncthreads();
    for (int u = start; u < cum; ++u) g_idx[n * MM + u] = t;
}

// ---------------- 3xBF16 HMMA GEMM + fused LN/ReLU + warp-specialized gather -
// 384 threads: warps 0-7 = GEMM (named barrier 1), warps 8-11 = gather half.
// SECOND=0: distributed epilogue scatters LN output into g_x2's 3 k-slots.
// SECOND=1: epilogue computes dur_out.
template <int SECOND>
__global__ void __launch_bounds__(384) gemm_ln_kernel(
    const float* __restrict__ bias, const float* __restrict__ gamma,
    const float* __restrict__ beta, const float* __restrict__ lw,
    const float* __restrict__ lbp, float* __restrict__ durout,
    const float* __restrict__ x, float* __restrict__ out)
{
    extern __shared__ char smem[];
    uint32_t sb = smem_u32(smem);
    int tid = threadIdx.x;

    if (tid >= 256) {
        // ---------------- gather warps (fully decoupled) ----------------
        int gt = tid - 256;                       // 0..127
        int w = gt >> 5, lane = gt & 31;
        int rbase = SECOND * GROWS_HALF + blockIdx.x * 256 + w * 64;
        const float4 zero = make_float4(0.f, 0.f, 0.f, 0.f);
        for (int rr = 0; rr < 64; rr += 4) {
            int js[4];
#pragma unroll
            for (int q = 0; q < 4; ++q) js[q] = g_idx[rbase + rr + q];
            float4 v[8];
#pragma unroll
            for (int q = 0; q < 4; ++q) {
                int grow = rbase + rr + q;
                if (js[q] >= 0) {
                    const float4* src = reinterpret_cast<const float4*>(
                        x + (size_t)((grow >> 12) * LL + js[q]) * EE);
                    v[2 * q]     = __ldg(src + lane * 2);
                    v[2 * q + 1] = __ldg(src + lane * 2 + 1);
                } else {
                    v[2 * q] = zero;
                    v[2 * q + 1] = zero;
                }
            }
#pragma unroll
            for (int q = 0; q < 4; ++q) {
                float4* dst = reinterpret_cast<float4*>(
                    out + (size_t)(rbase + rr + q) * EE);
                __stwt(dst + lane * 2, v[2 * q]);          // streaming: keep out of L2
                __stwt(dst + lane * 2 + 1, v[2 * q + 1]);
            }
        }
        return;
    }

    // ---------------- GEMM warp group (tid < 256) ----------------
    int wid = tid >> 5, lane = tid & 31;
    int m0 = blockIdx.x * 64;
    int wm = wid & 1, wn = wid >> 1;
    int g = lane >> 2, t = lane & 3;
    const __nv_bfloat16* Ah = SECOND ? g_xh2 : g_xh1;
    const __nv_bfloat16* Al = SECOND ? g_xl2 : g_xl1;
    const __nv_bfloat16* Bh = SECOND ? g_wh2 : g_wh1;
    const __nv_bfloat16* Bl = SECOND ? g_wl2 : g_wl1;

    {
        float* pp = reinterpret_cast<float*>(smem + SM_PAR);
        pp[tid] = bias[tid];
        pp[256 + tid] = gamma[tid];
        pp[512 + tid] = beta[tid];
        pp[768 + tid] = SECOND ? lw[tid] : 0.f;
    }

    int a_row = (((lane >> 3) & 1) << 3) + (lane & 7);
    int a_kb  = (lane >> 4) << 4;
    int b_row = ((lane >> 4) << 3) + (lane & 7);
    int b_kb  = ((lane >> 3) & 1) << 4;

    auto issue_chunk = [&](int c, int buf) {
        uint32_t sa = sb + buf * STAGE;
        uint32_t sbm = sa + ASZ;
        size_t aoff = ((size_t)m0 * KTOT + c * KC) * 2;
        size_t boff = (size_t)c * KC * 2;
        const char* gAh = reinterpret_cast<const char*>(Ah) + aoff;
        const char* gAl = reinterpret_cast<const char*>(Al) + aoff;
        const char* gBh = reinterpret_cast<const char*>(Bh) + boff;
        const char* gBl = reinterpret_cast<const char*>(Bl) + boff;
#pragma unroll
        for (int i = 0; i < 2; ++i) {          // A: 64 rows x 8 segs per plane
            int lin = tid + (i << 8);
            int row = lin >> 3, seg = lin & 7;
            cp16(sa + row * ROWB + seg * 16, gAh + (size_t)row * 1536 + seg * 16);
            cp16(sa + (64 + row) * ROWB + seg * 16, gAl + (size_t)row * 1536 + seg * 16);
        }
#pragma unroll
        for (int i = 0; i < 8; ++i) {          // B: 256 rows x 8 segs, both planes
            int lin = tid + (i << 8);
            int row = lin >> 3, seg = lin & 7;
            cp16(sbm + row * ROWB + seg * 16, gBh + (size_t)row * 1536 + seg * 16);
            cp16(sbm + (256 + row) * ROWB + seg * 16, gBl + (size_t)row * 1536 + seg * 16);
        }
        CP_COMMIT();
    };

    float acc[2][8][4];
#pragma unroll
    for (int mt = 0; mt < 2; ++mt)
#pragma unroll
        for (int nt = 0; nt < 8; ++nt)
#pragma unroll
            for (int q = 0; q < 4; ++q) acc[mt][nt][q] = 0.f;

    issue_chunk(0, 0);
    for (int c = 0; c < NCHUNK; ++c) {
        int buf = c & 1;
        if (c + 1 < NCHUNK) {
            issue_chunk(c + 1, buf ^ 1);
            cp_wait<1>();
        } else {
            cp_wait<0>();
        }
        BARG();
        uint32_t abase = sb + buf * STAGE;
        uint32_t bbase = abase + ASZ;
#pragma unroll
        for (int ks = 0; ks < 4; ++ks) {
            int k0 = ks * 16;
            uint32_t fAh[2][4], fAl[2][4];
            uint32_t fBh[8][2], fBl[8][2];
#pragma unroll
            for (int mt = 0; mt < 2; ++mt) {
                uint32_t ra = abase + (wm * 32 + mt * 16 + a_row) * ROWB + k0 * 2 + a_kb;
                ldsm4(fAh[mt], ra);
                ldsm4(fAl[mt], ra + 64 * ROWB);
            }
#pragma unroll
            for (int np = 0; np < 4; ++np) {
                uint32_t rb = bbase + (wn * 64 + np * 16 + b_row) * ROWB + k0 * 2 + b_kb;
                uint32_t r[4];
                ldsm4(r, rb);
                fBh[2 * np][0] = r[0]; fBh[2 * np][1] = r[1];
                fBh[2 * np + 1][0] = r[2]; fBh[2 * np + 1][1] = r[3];
                ldsm4(r, rb + 256 * ROWB);
                fBl[2 * np][0] = r[0]; fBl[2 * np][1] = r[1];
                fBl[2 * np + 1][0] = r[2]; fBl[2 * np + 1][1] = r[3];
            }
#pragma unroll
            for (int mt = 0; mt < 2; ++mt) {
#pragma unroll
                for (int nt = 0; nt < 8; ++nt)
                    mma_bf16(acc[mt][nt], fAh[mt][0], fAh[mt][1], fAh[mt][2], fAh[mt][3],
                             fBh[nt][0], fBh[nt][1]);
#pragma unroll
                for (int nt = 0; nt < 8; ++nt)
                    mma_bf16(acc[mt][nt], fAh[mt][0], fAh[mt][1], fAh[mt][2], fAh[mt][3],
                             fBl[nt][0], fBl[nt][1]);
#pragma unroll
                for (int nt = 0; nt < 8; ++nt)
                    mma_bf16(acc[mt][nt], fAl[mt][0], fAl[mt][1], fAl[mt][2], fAl[mt][3],
                             fBh[nt][0], fBh[nt][1]);
            }
        }
        BARG();
    }

    // ---------------- epilogue ----------------
    float* ot = reinterpret_cast<float*>(smem);   // [64][260] fp32, reuses stage 0
#pragma unroll
    for (int mt = 0; mt < 2; ++mt)
#pragma unroll
        for (int nt = 0; nt < 8; ++nt) {
            int m = wm * 32 + mt * 16 + g;
            int n = wn * 64 + nt * 8 + 2 * t;
            *reinterpret_cast<float2*>(ot + m * 260 + n) =
                make_float2(acc[mt][nt][0], acc[mt][nt][1]);
            *reinterpret_cast<float2*>(ot + (m + 8) * 260 + n) =
                make_float2(acc[mt][nt][2], acc[mt][nt][3]);
        }
    BARG();

    const float* pb = reinterpret_cast<const float*>(smem + SM_PAR);
    const float* pg = pb + 256;
    const float* pe = pb + 512;
    const float* pl = pb + 768;
    float2* mus = reinterpret_cast<float2*>(smem + SM_MU);

    // Phase A: 64 threads compute LN stats (streaming; no big register array)
    if (tid < 64) {
        const float* rowp = ot + tid * 260;
        float s = 0.f, ss = 0.f;
#pragma unroll 4
        for (int j = 0; j < 256; j += 4) {
            float4 v4 = *reinterpret_cast<const float4*>(rowp + j);
            float h0 = v4.x + pb[j], h1 = v4.y + pb[j + 1];
            float h2 = v4.z + pb[j + 2], h3 = v4.w + pb[j + 3];
            s += h0 + h1 + h2 + h3;
            ss += h0 * h0 + h1 * h1 + h2 * h2 + h3 * h3;
        }
        float mu = s * (1.f / 256.f);
        float var = ss * (1.f / 256.f) - mu * mu;
        mus[tid] = make_float2(mu, rsqrtf(var + 1e-5f));
    }
    BARG();

    if (!SECOND) {
        // Phase B: all 256 threads scatter (4 threads per row, 64 cols each)
        int row_l = tid & 63;                 // local row
        int part = tid >> 6;                  // 0..3
        int row = m0 + row_l;
        int l = row & 511;
        float2 mr = mus[row_l];
        float mu = mr.x, rs = mr.y;
        const float* rowp = ot + row_l * 260;
#pragma unroll
        for (int jj = 0; jj < 64; jj += 8) {
            int j = part * 64 + jj;
            uint32_t wh[4], wl[4];
#pragma unroll
            for (int q = 0; q < 4; ++q) {
                float v0 = rowp[j + 2 * q] + pb[j + 2 * q];
                float v1 = rowp[j + 2 * q + 1] + pb[j + 2 * q + 1];
                float y0 = fmaxf(0.f, (v0 - mu) * rs * pg[j + 2 * q] + pe[j + 2 * q]);
                float y1 = fmaxf(0.f, (v1 - mu) * rs * pg[j + 2 * q + 1] + pe[j + 2 * q + 1]);
                __nv_bfloat16 h0, l0, h1, l1;
                split_bf16(y0, h0, l0);
                split_bf16(y1, h1, l1);
                wh[q] = ((uint32_t)*reinterpret_cast<uint16_t*>(&h1) << 16) |
                        *reinterpret_cast<uint16_t*>(&h0);
                wl[q] = ((uint32_t)*reinterpret_cast<uint16_t*>(&l1) << 16) |
                        *reinterpret_cast<uint16_t*>(&l0);
            }
            uint4 vh = make_uint4(wh[0], wh[1], wh[2], wh[3]);
            uint4 vl = make_uint4(wl[0], wl[1], wl[2], wl[3]);
            // k=1 slot at row
            *reinterpret_cast<uint4*>(g_xh2 + (size_t)row * KTOT + 256 + j) = vh;
            *reinterpret_cast<uint4*>(g_xl2 + (size_t)row * KTOT + 256 + j) = vl;
            // k=0 slot at row+1
            if (l < 511) {
                *reinterpret_cast<uint4*>(g_xh2 + (size_t)(row + 1) * KTOT + j) = vh;
                *reinterpret_cast<uint4*>(g_xl2 + (size_t)(row + 1) * KTOT + j) = vl;
            }
            // k=2 slot at row-1
            if (l > 0) {
                *reinterpret_cast<uint4*>(g_xh2 + (size_t)(row - 1) * KTOT + 512 + j) = vh;
                *reinterpret_cast<uint4*>(g_xl2 + (size_t)(row - 1) * KTOT + 512 + j) = vl;
            }
        }
    } else {
        if (tid < 64) {
            float2 mr = mus[tid];
            float mu = mr.x, rs = mr.y;
            const float* rowp = ot + tid * 260;
            float dacc = 0.f;
#pragma unroll 4
            for (int j = 0; j < 256; ++j) {
                float y = fmaxf(0.f, (rowp[j] + pb[j] - mu) * rs * pg[j] + pe[j]);
                dacc += y * pl[j];
            }
            durout[m0 + tid] = fmaxf(0.f, dacc + *lbp);
        }
    }
}

// ---------------- launch ----------------
extern "C" void kernel_launch(void* const* d_in, const int* in_sizes, int n_in,
                              void* d_out, int out_size) {
    const float* x   = (const float*)d_in[0];
    const float* c1w = (const float*)d_in[1];
    const float* c1b = (const float*)d_in[2];
    const float* l1g = (const float*)d_in[3];
    const float* l1b = (const float*)d_in[4];
    const float* c2w = (const float*)d_in[5];
    const float* c2b = (const float*)d_in[6];
    const float* l2g = (const float*)d_in[7];
    const float* l2b = (const float*)d_in[8];
    const float* lw  = (const float*)d_in[9];
    const float* lb  = (const float*)d_in[10];
    const int* target = (const int*)d_in[11];
    float* out = (float*)d_out;

    cudaFuncSetAttribute(gemm_ln_kernel<0>, cudaFuncAttributeMaxDynamicSharedMemorySize, SM_TOTAL);
    cudaFuncSetAttribute(gemm_ln_kernel<1>, cudaFuncAttributeMaxDynamicSharedMemorySize, SM_TOTAL);

    prep_w_kernel<<<dim3(256, 2), 256>>>(c1w, c2w);
    im2col_kernel<<<NROWS / 8, 256>>>(x);
    build_idx_kernel<<<16, 512>>>(target);
    gemm_ln_kernel<0><<<128, 384, SM_TOTAL>>>(c1b, l1g, l1b, lw, lb, nullptr, x, out);
    gemm_ln_kernel<1><<<128, 384, SM_TOTAL>>>(c2b, l2g, l2b, lw, lb, out + OUT_ELEMS, x, out);
}

// round 15
// speedup vs baseline: 1.7803x; 1.1784x over previous
#include <cuda_runtime.h>
#include <cuda_bf16.h>
#include <cstdint>

#define NB 16
#define LL 512
#define EE 256
#define FF 256
#define MM 4096
#define OUT_ELEMS (NB * MM * EE)   // 16777216
#define KTOT 768
#define NROWS (NB * LL)            // 8192
#define KC 64                      // K chunk (bf16)
#define NCHUNK (KTOT / KC)         // 12
#define PADK 72                    // padded row length (bf16) -> 144 B
#define ROWB (PADK * 2)            // 144 bytes
#define GROWS_HALF (NB * MM / 2)   // 32768 gather rows per gemm kernel

// ---------------- scratch: compact [row][256] hi/lo planes -------------------
__device__ __nv_bfloat16 g_xh[NROWS * EE];    // x  hi (4 MB)
__device__ __nv_bfloat16 g_xl[NROWS * EE];    // x  lo
__device__ __nv_bfloat16 g_h1h[NROWS * FF];   // h1 hi
__device__ __nv_bfloat16 g_h1l[NROWS * FF];   // h1 lo
__device__ __nv_bfloat16 g_wh1[FF * KTOT];
__device__ __nv_bfloat16 g_wl1[FF * KTOT];
__device__ __nv_bfloat16 g_wh2[FF * KTOT];
__device__ __nv_bfloat16 g_wl2[FF * KTOT];
__device__ int           g_idx[NB * MM];

// ---------------- smem layout ----------------
#define ASZ   (128 * ROWB)             // A_hi rows 0-63, A_lo rows 64-127
#define BSZ   (512 * ROWB)             // B_hi rows 0-255, B_lo rows 256-511
#define STAGE (ASZ + BSZ)              // 92160
#define SM_PAR (2 * STAGE)             // 184320: bias|gamma|beta|lw (4 KB)
#define SM_MU  (SM_PAR + 4096)         // 64 x float2 (mu, rs)
#define SM_TOTAL (SM_MU + 512)         // 188928

// ---------------- helpers ----------------
__device__ __forceinline__ uint32_t smem_u32(const void* p) {
    uint32_t a;
    asm("{ .reg .u64 t; cvta.to.shared.u64 t, %1; cvt.u32.u64 %0, t; }" : "=r"(a) : "l"(p));
    return a;
}
__device__ __forceinline__ void cp16(uint32_t dst, const void* src) {
    asm volatile("cp.async.cg.shared.global [%0], [%1], 16;" :: "r"(dst), "l"(src));
}
// zero-fill variant: copies src_sz bytes (0 or 16), zero-fills the rest
__device__ __forceinline__ void cp16z(uint32_t dst, const void* src, uint32_t src_sz) {
    asm volatile("cp.async.cg.shared.global [%0], [%1], 16, %2;"
                 :: "r"(dst), "l"(src), "r"(src_sz));
}
#define CP_COMMIT() asm volatile("cp.async.commit_group;" ::: "memory")
template <int N>
__device__ __forceinline__ void cp_wait() {
    asm volatile("cp.async.wait_group %0;" :: "n"(N) : "memory");
}
// named barrier: GEMM warp group only (256 threads); gather warps never arrive
#define BARG() asm volatile("bar.sync 1, 256;" ::: "memory")
__device__ __forceinline__ void ldsm4(uint32_t* r, uint32_t addr) {
    asm volatile("ldmatrix.sync.aligned.m8n8.x4.shared.b16 {%0,%1,%2,%3}, [%4];"
                 : "=r"(r[0]), "=r"(r[1]), "=r"(r[2]), "=r"(r[3]) : "r"(addr));
}
__device__ __forceinline__ void mma_bf16(float* d, uint32_t a0, uint32_t a1,
                                         uint32_t a2, uint32_t a3,
                                         uint32_t b0, uint32_t b1) {
    asm("mma.sync.aligned.m16n8k16.row.col.f32.bf16.bf16.f32 "
        "{%0,%1,%2,%3}, {%4,%5,%6,%7}, {%8,%9}, {%0,%1,%2,%3};"
        : "+f"(d[0]), "+f"(d[1]), "+f"(d[2]), "+f"(d[3])
        : "r"(a0), "r"(a1), "r"(a2), "r"(a3), "r"(b0), "r"(b1));
}
__device__ __forceinline__ void split_bf16(float v, __nv_bfloat16& hi, __nv_bfloat16& lo) {
    hi = __float2bfloat16(v);
    lo = __float2bfloat16(v - __bfloat162float(hi));
}

// ---------------- weight prep ----------------
__global__ void prep_w_kernel(const float* __restrict__ w1, const float* __restrict__ w2) {
    int f = blockIdx.x;
    const float* w = blockIdx.y ? w2 : w1;
    __nv_bfloat16* wh = blockIdx.y ? g_wh2 : g_wh1;
    __nv_bfloat16* wl = blockIdx.y ? g_wl2 : g_wl1;
    int e = threadIdx.x;
#pragma unroll
    for (int k = 0; k < 3; ++k) {
        __nv_bfloat16 hi, lo;
        split_bf16(w[f * KTOT + e * 3 + k], hi, lo);
        wh[f * KTOT + k * 256 + e] = hi;
        wl[f * KTOT + k * 256 + e] = lo;
    }
}

// ---------------- convert x: fp32 -> compact hi/lo [row][256] ----------------
__global__ void __launch_bounds__(256) conv_x_kernel(const float* __restrict__ x) {
    int warp = threadIdx.x >> 5, lane = threadIdx.x & 31;
    int row = blockIdx.x * 8 + warp;
    int e0 = lane * 8;
    const float* xr = x + ((size_t)row * EE + e0);
    uint4 vh, vl;
    uint32_t* ph = reinterpret_cast<uint32_t*>(&vh);
    uint32_t* pl = reinterpret_cast<uint32_t*>(&vl);
#pragma unroll
    for (int q = 0; q < 4; ++q) {
        __nv_bfloat16 h0, l0, h1, l1;
        split_bf16(xr[2 * q], h0, l0);
        split_bf16(xr[2 * q + 1], h1, l1);
        ph[q] = ((uint32_t)*reinterpret_cast<uint16_t*>(&h1) << 16) |
                *reinterpret_cast<uint16_t*>(&h0);
        pl[q] = ((uint32_t)*reinterpret_cast<uint16_t*>(&l1) << 16) |
                *reinterpret_cast<uint16_t*>(&l0);
    }
    *reinterpret_cast<uint4*>(g_xh + (size_t)row * EE + e0) = vh;
    *reinterpret_cast<uint4*>(g_xl + (size_t)row * EE + e0) = vl;
}

// ---------------- build idx map ----------------
__global__ void build_idx_kernel(const int* __restrict__ target) {
    int n = blockIdx.x, t = threadIdx.x;
    __shared__ int s[512];
    int d = target[n * LL + t];
    s[t] = d;
    __syncthreads();
    for (int off = 1; off < 512; off <<= 1) {
        int v = (t >= off) ? s[t - off] : 0;
        __syncthreads();
        s[t] += v;
        __syncthreads();
    }
    int cum = s[t], start = cum - d;
    for (int i = t; i < MM; i += 512) g_idx[n * MM + i] = -1;
    __syncthreads();
    for (int u = start; u < cum; ++u) g_idx[n * MM + u] = t;
}

// ---------------- 3xBF16 HMMA GEMM + fused LN/ReLU + warp-specialized gather -
// 384 threads: warps 0-7 = GEMM (named barrier 1), warps 8-11 = gather half.
// A is read from compact [row][256] planes; chunk c maps to conv k-slot
// slot=c/4, e-range (c%4)*64, source row = row + slot - 1 (zero-filled at
// sequence boundaries via cp.async src-size=0).
// SECOND=0: epilogue stores h1 (hi/lo) contiguously; SECOND=1: dur_out.
template <int SECOND>
__global__ void __launch_bounds__(384) gemm_ln_kernel(
    const float* __restrict__ bias, const float* __restrict__ gamma,
    const float* __restrict__ beta, const float* __restrict__ lw,
    const float* __restrict__ lbp, float* __restrict__ durout,
    const float* __restrict__ x, float* __restrict__ out)
{
    extern __shared__ char smem[];
    uint32_t sb = smem_u32(smem);
    int tid = threadIdx.x;

    if (tid >= 256) {
        // ---------------- gather warps (fully decoupled) ----------------
        int gt = tid - 256;                       // 0..127
        int w = gt >> 5, lane = gt & 31;
        int rbase = SECOND * GROWS_HALF + blockIdx.x * 256 + w * 64;
        const float4 zero = make_float4(0.f, 0.f, 0.f, 0.f);
        for (int rr = 0; rr < 64; rr += 4) {
            int js[4];
#pragma unroll
            for (int q = 0; q < 4; ++q) js[q] = g_idx[rbase + rr + q];
            float4 v[8];
#pragma unroll
            for (int q = 0; q < 4; ++q) {
                int grow = rbase + rr + q;
                if (js[q] >= 0) {
                    const float4* src = reinterpret_cast<const float4*>(
                        x + (size_t)((grow >> 12) * LL + js[q]) * EE);
                    v[2 * q]     = __ldg(src + lane * 2);
                    v[2 * q + 1] = __ldg(src + lane * 2 + 1);
                } else {
                    v[2 * q] = zero;
                    v[2 * q + 1] = zero;
                }
            }
#pragma unroll
            for (int q = 0; q < 4; ++q) {
                float4* dst = reinterpret_cast<float4*>(
                    out + (size_t)(rbase + rr + q) * EE);
                __stwt(dst + lane * 2, v[2 * q]);          // streaming: keep out of L2
                __stwt(dst + lane * 2 + 1, v[2 * q + 1]);
            }
        }
        return;
    }

    // ---------------- GEMM warp group (tid < 256) ----------------
    int wid = tid >> 5, lane = tid & 31;
    int m0 = blockIdx.x * 64;
    int wm = wid & 1, wn = wid >> 1;
    int g = lane >> 2, t = lane & 3;
    const __nv_bfloat16* Ah = SECOND ? g_h1h : g_xh;
    const __nv_bfloat16* Al = SECOND ? g_h1l : g_xl;
    const __nv_bfloat16* Bh = SECOND ? g_wh2 : g_wh1;
    const __nv_bfloat16* Bl = SECOND ? g_wl2 : g_wl1;

    {
        float* pp = reinterpret_cast<float*>(smem + SM_PAR);
        pp[tid] = bias[tid];
        pp[256 + tid] = gamma[tid];
        pp[512 + tid] = beta[tid];
        pp[768 + tid] = SECOND ? lw[tid] : 0.f;
    }

    int a_row = (((lane >> 3) & 1) << 3) + (lane & 7);
    int a_kb  = (lane >> 4) << 4;
    int b_row = ((lane >> 4) << 3) + (lane & 7);
    int b_kb  = ((lane >> 3) & 1) << 4;

    auto issue_chunk = [&](int c, int buf) {
        uint32_t sa = sb + buf * STAGE;
        uint32_t sbm = sa + ASZ;
        int slot = c >> 2;                      // conv k index 0..2
        int e0c = (c & 3) << 6;                 // 0,64,128,192 (bf16 elems)
        // A: row r -> source row (m0+r) + slot - 1, zero-fill at seq boundary
#pragma unroll
        for (int i = 0; i < 2; ++i) {
            int lin = tid + (i << 8);
            int row = lin >> 3, seg = lin & 7;  // 64 rows x 8 segs (seg=16B=8 elems)
            int grow = m0 + row;
            int l = grow & 511;
            int sl = l + slot - 1;
            uint32_t ok = (sl >= 0 && sl < LL) ? 16u : 0u;
            size_t srow = ok ? (size_t)(grow + slot - 1) : 0;
            const char* srch = reinterpret_cast<const char*>(Ah) +
                               (srow * EE + e0c) * 2 + seg * 16;
            const char* srcl = reinterpret_cast<const char*>(Al) +
                               (srow * EE + e0c) * 2 + seg * 16;
            cp16z(sa + row * ROWB + seg * 16, srch, ok);
            cp16z(sa + (64 + row) * ROWB + seg * 16, srcl, ok);
        }
        // B: 256 rows x 8 segs, both planes (K-major [f][768])
        size_t boff = (size_t)c * KC * 2;
        const char* gBh = reinterpret_cast<const char*>(Bh) + boff;
        const char* gBl = reinterpret_cast<const char*>(Bl) + boff;
#pragma unroll
        for (int i = 0; i < 8; ++i) {
            int lin = tid + (i << 8);
            int row = lin >> 3, seg = lin & 7;
            cp16(sbm + row * ROWB + seg * 16, gBh + (size_t)row * 1536 + seg * 16);
            cp16(sbm + (256 + row) * ROWB + seg * 16, gBl + (size_t)row * 1536 + seg * 16);
        }
        CP_COMMIT();
    };

    float acc[2][8][4];
#pragma unroll
    for (int mt = 0; mt < 2; ++mt)
#pragma unroll
        for (int nt = 0; nt < 8; ++nt)
#pragma unroll
            for (int q = 0; q < 4; ++q) acc[mt][nt][q] = 0.f;

    issue_chunk(0, 0);
    for (int c = 0; c < NCHUNK; ++c) {
        int buf = c & 1;
        if (c + 1 < NCHUNK) {
            issue_chunk(c + 1, buf ^ 1);
            cp_wait<1>();
        } else {
            cp_wait<0>();
        }
        BARG();
        uint32_t abase = sb + buf * STAGE;
        uint32_t bbase = abase + ASZ;
#pragma unroll
        for (int ks = 0; ks < 4; ++ks) {
            int k0 = ks * 16;
            uint32_t fAh[2][4], fAl[2][4];
            uint32_t fBh[8][2], fBl[8][2];
#pragma unroll
            for (int mt = 0; mt < 2; ++mt) {
                uint32_t ra = abase + (wm * 32 + mt * 16 + a_row) * ROWB + k0 * 2 + a_kb;
                ldsm4(fAh[mt], ra);
                ldsm4(fAl[mt], ra + 64 * ROWB);
            }
#pragma unroll
            for (int np = 0; np < 4; ++np) {
                uint32_t rb = bbase + (wn * 64 + np * 16 + b_row) * ROWB + k0 * 2 + b_kb;
                uint32_t r[4];
                ldsm4(r, rb);
                fBh[2 * np][0] = r[0]; fBh[2 * np][1] = r[1];
                fBh[2 * np + 1][0] = r[2]; fBh[2 * np + 1][1] = r[3];
                ldsm4(r, rb + 256 * ROWB);
                fBl[2 * np][0] = r[0]; fBl[2 * np][1] = r[1];
                fBl[2 * np + 1][0] = r[2]; fBl[2 * np + 1][1] = r[3];
            }
#pragma unroll
            for (int mt = 0; mt < 2; ++mt) {
#pragma unroll
                for (int nt = 0; nt < 8; ++nt)
                    mma_bf16(acc[mt][nt], fAh[mt][0], fAh[mt][1], fAh[mt][2], fAh[mt][3],
                             fBh[nt][0], fBh[nt][1]);
#pragma unroll
                for (int nt = 0; nt < 8; ++nt)
                    mma_bf16(acc[mt][nt], fAh[mt][0], fAh[mt][1], fAh[mt][2], fAh[mt][3],
                             fBl[nt][0], fBl[nt][1]);
#pragma unroll
                for (int nt = 0; nt < 8; ++nt)
                    mma_bf16(acc[mt][nt], fAl[mt][0], fAl[mt][1], fAl[mt][2], fAl[mt][3],
                             fBh[nt][0], fBh[nt][1]);
            }
        }
        BARG();
    }

    // ---------------- epilogue ----------------
    float* ot = reinterpret_cast<float*>(smem);   // [64][260] fp32, reuses stage 0
#pragma unroll
    for (int mt = 0; mt < 2; ++mt)
#pragma unroll
        for (int nt = 0; nt < 8; ++nt) {
            int m = wm * 32 + mt * 16 + g;
            int n = wn * 64 + nt * 8 + 2 * t;
            *reinterpret_cast<float2*>(ot + m * 260 + n) =
                make_float2(acc[mt][nt][0], acc[mt][nt][1]);
            *reinterpret_cast<float2*>(ot + (m + 8) * 260 + n) =
                make_float2(acc[mt][nt][2], acc[mt][nt][3]);
        }
    BARG();

    const float* pb = reinterpret_cast<const float*>(smem + SM_PAR);
    const float* pg = pb + 256;
    const float* pe = pb + 512;
    const float* pl = pb + 768;
    float2* mus = reinterpret_cast<float2*>(smem + SM_MU);

    // Phase A: 64 threads compute LN stats (streaming)
    if (tid < 64) {
        const float* rowp = ot + tid * 260;
        float s = 0.f, ss = 0.f;
#pragma unroll 4
        for (int j = 0; j < 256; j += 4) {
            float4 v4 = *reinterpret_cast<const float4*>(rowp + j);
            float h0 = v4.x + pb[j], h1 = v4.y + pb[j + 1];
            float h2 = v4.z + pb[j + 2], h3 = v4.w + pb[j + 3];
            s += h0 + h1 + h2 + h3;
            ss += h0 * h0 + h1 * h1 + h2 * h2 + h3 * h3;
        }
        float mu = s * (1.f / 256.f);
        float var = ss * (1.f / 256.f) - mu * mu;
        mus[tid] = make_float2(mu, rsqrtf(var + 1e-5f));
    }
    BARG();

    if (!SECOND) {
        // Phase B: all 256 threads, 4 per row; contiguous h1 store (once!)
        int row_l = tid & 63;
        int part = tid >> 6;
        int row = m0 + row_l;
        float2 mr = mus[row_l];
        float mu = mr.x, rs = mr.y;
        const float* rowp = ot + row_l * 260;
#pragma unroll
        for (int jj = 0; jj < 64; jj += 8) {
            int j = part * 64 + jj;
            uint32_t wh[4], wl[4];
#pragma unroll
            for (int q = 0; q < 4; ++q) {
                float v0 = rowp[j + 2 * q] + pb[j + 2 * q];
                float v1 = rowp[j + 2 * q + 1] + pb[j + 2 * q + 1];
                float y0 = fmaxf(0.f, (v0 - mu) * rs * pg[j + 2 * q] + pe[j + 2 * q]);
                float y1 = fmaxf(0.f, (v1 - mu) * rs * pg[j + 2 * q + 1] + pe[j + 2 * q + 1]);
                __nv_bfloat16 h0, l0, h1, l1;
                split_bf16(y0, h0, l0);
                split_bf16(y1, h1, l1);
                wh[q] = ((uint32_t)*reinterpret_cast<uint16_t*>(&h1) << 16) |
                        *reinterpret_cast<uint16_t*>(&h0);
                wl[q] = ((uint32_t)*reinterpret_cast<uint16_t*>(&l1) << 16) |
                        *reinterpret_cast<uint16_t*>(&l0);
            }
            *reinterpret_cast<uint4*>(g_h1h + (size_t)row * FF + j) =
                make_uint4(wh[0], wh[1], wh[2], wh[3]);
            *reinterpret_cast<uint4*>(g_h1l + (size_t)row * FF + j) =
                make_uint4(wl[0], wl[1], wl[2], wl[3]);
        }
    } else {
        if (tid < 64) {
            float2 mr = mus[tid];
            float mu = mr.x, rs = mr.y;
            const float* rowp = ot + tid * 260;
            float dacc = 0.f;
#pragma unroll 4
            for (int j = 0; j < 256; ++j) {
                float y = fmaxf(0.f, (rowp[j] + pb[j] - mu) * rs * pg[j] + pe[j]);
                dacc += y * pl[j];
            }
            durout[m0 + tid] = fmaxf(0.f, dacc + *lbp);
        }
    }
}

// ---------------- launch ----------------
extern "C" void kernel_launch(void* const* d_in, const int* in_sizes, int n_in,
                              void* d_out, int out_size) {
    const float* x   = (const float*)d_in[0];
    const float* c1w = (const float*)d_in[1];
    const float* c1b = (const float*)d_in[2];
    const float* l1g = (const float*)d_in[3];
    const float* l1b = (const float*)d_in[4];
    const float* c2w = (const float*)d_in[5];
    const float* c2b = (const float*)d_in[6];
    const float* l2g = (const float*)d_in[7];
    const float* l2b = (const float*)d_in[8];
    const float* lw  = (const float*)d_in[9];
    const float* lb  = (const float*)d_in[10];
    const int* target = (const int*)d_in[11];
    float* out = (float*)d_out;

    cudaFuncSetAttribute(gemm_ln_kernel<0>, cudaFuncAttributeMaxDynamicSharedMemorySize, SM_TOTAL);
    cudaFuncSetAttribute(gemm_ln_kernel<1>, cudaFuncAttributeMaxDynamicSharedMemorySize, SM_TOTAL);

    prep_w_kernel<<<dim3(256, 2), 256>>>(c1w, c2w);
    conv_x_kernel<<<NROWS / 8, 256>>>(x);
    build_idx_kernel<<<16, 512>>>(target);
    gemm_ln_kernel<0><<<128, 384, SM_TOTAL>>>(c1b, l1g, l1b, lw, lb, nullptr, x, out);
    gemm_ln_kernel<1><<<128, 384, SM_TOTAL>>>(c2b, l2g, l2b, lw, lb, out + OUT_ELEMS, x, out);
}

// round 16
// speedup vs baseline: 1.8939x; 1.0638x over previous
#include <cuda_runtime.h>
#include <cuda_bf16.h>
#include <cstdint>

#define NB 16
#define LL 512
#define EE 256
#define FF 256
#define MM 4096
#define OUT_ELEMS (NB * MM * EE)   // 16777216
#define KTOT 768
#define NROWS (NB * LL)            // 8192
#define KC 64                      // K chunk (bf16)
#define NCHUNK (KTOT / KC)         // 12
#define PADK 72                    // padded row length (bf16) -> 144 B
#define ROWB (PADK * 2)            // 144 bytes
#define GROWS_HALF (NB * MM / 2)   // 32768 gather rows per gemm kernel
#define GEMM_CTAS 128
#define GATH_CTAS 20
#define GRID (GEMM_CTAS + GATH_CTAS)   // 148
#define ROWS_PER_GEMM_CTA 192          // 128*192 = 24576
#define ROWS_GEMM_TOTAL (GEMM_CTAS * ROWS_PER_GEMM_CTA)
#define ROWS_PER_GATH_CTA 410          // ceil(8192/20)

// ---------------- scratch: compact [row][256] hi/lo planes -------------------
__device__ __nv_bfloat16 g_xh[NROWS * EE];    // x  hi (4 MB)
__device__ __nv_bfloat16 g_xl[NROWS * EE];    // x  lo
__device__ __nv_bfloat16 g_h1h[NROWS * FF];   // h1 hi
__device__ __nv_bfloat16 g_h1l[NROWS * FF];   // h1 lo
__device__ __nv_bfloat16 g_wh1[FF * KTOT];
__device__ __nv_bfloat16 g_wl1[FF * KTOT];
__device__ __nv_bfloat16 g_wh2[FF * KTOT];
__device__ __nv_bfloat16 g_wl2[FF * KTOT];
__device__ int           g_idx[NB * MM];

// ---------------- smem layout ----------------
#define ASZ   (128 * ROWB)             // A_hi rows 0-63, A_lo rows 64-127
#define BSZ   (512 * ROWB)             // B_hi rows 0-255, B_lo rows 256-511
#define STAGE (ASZ + BSZ)              // 92160
#define SM_PAR (2 * STAGE)             // 184320: bias|gamma|beta|lw (4 KB)
#define SM_MU  (SM_PAR + 4096)         // 64 x float2 (mu, rs)
#define SM_TOTAL (SM_MU + 512)         // 188928

// ---------------- helpers ----------------
__device__ __forceinline__ uint32_t smem_u32(const void* p) {
    uint32_t a;
    asm("{ .reg .u64 t; cvta.to.shared.u64 t, %1; cvt.u32.u64 %0, t; }" : "=r"(a) : "l"(p));
    return a;
}
__device__ __forceinline__ void cp16(uint32_t dst, const void* src) {
    asm volatile("cp.async.cg.shared.global [%0], [%1], 16;" :: "r"(dst), "l"(src));
}
__device__ __forceinline__ void cp16z(uint32_t dst, const void* src, uint32_t src_sz) {
    asm volatile("cp.async.cg.shared.global [%0], [%1], 16, %2;"
                 :: "r"(dst), "l"(src), "r"(src_sz));
}
#define CP_COMMIT() asm volatile("cp.async.commit_group;" ::: "memory")
template <int N>
__device__ __forceinline__ void cp_wait() {
    asm volatile("cp.async.wait_group %0;" :: "n"(N) : "memory");
}
#define BARG() asm volatile("bar.sync 1, 256;" ::: "memory")
__device__ __forceinline__ void ldsm4(uint32_t* r, uint32_t addr) {
    asm volatile("ldmatrix.sync.aligned.m8n8.x4.shared.b16 {%0,%1,%2,%3}, [%4];"
                 : "=r"(r[0]), "=r"(r[1]), "=r"(r[2]), "=r"(r[3]) : "r"(addr));
}
__device__ __forceinline__ void mma_bf16(float* d, uint32_t a0, uint32_t a1,
                                         uint32_t a2, uint32_t a3,
                                         uint32_t b0, uint32_t b1) {
    asm("mma.sync.aligned.m16n8k16.row.col.f32.bf16.bf16.f32 "
        "{%0,%1,%2,%3}, {%4,%5,%6,%7}, {%8,%9}, {%0,%1,%2,%3};"
        : "+f"(d[0]), "+f"(d[1]), "+f"(d[2]), "+f"(d[3])
        : "r"(a0), "r"(a1), "r"(a2), "r"(a3), "r"(b0), "r"(b1));
}
__device__ __forceinline__ void split_bf16(float v, __nv_bfloat16& hi, __nv_bfloat16& lo) {
    hi = __float2bfloat16(v);
    lo = __float2bfloat16(v - __bfloat162float(hi));
}

// ---------------- fused prep: conv_x | prep_w | build_idx --------------------
// blocks [0,512): conv_x (16 rows each); [512,768): prep_w (f = bid-512);
// blocks [768,784): build_idx (n = bid-768).  512 threads everywhere.
__global__ void __launch_bounds__(512) prep_kernel(
    const float* __restrict__ x,
    const float* __restrict__ w1, const float* __restrict__ w2,
    const int* __restrict__ target)
{
    int bid = blockIdx.x, tid = threadIdx.x;
    if (bid < 512) {
        int warp = tid >> 5, lane = tid & 31;
        int row = bid * 16 + warp;
        int e0 = lane * 8;
        const float* xr = x + ((size_t)row * EE + e0);
        uint4 vh, vl;
        uint32_t* ph = reinterpret_cast<uint32_t*>(&vh);
        uint32_t* pl = reinterpret_cast<uint32_t*>(&vl);
#pragma unroll
        for (int q = 0; q < 4; ++q) {
            __nv_bfloat16 h0, l0, h1, l1;
            split_bf16(xr[2 * q], h0, l0);
            split_bf16(xr[2 * q + 1], h1, l1);
            ph[q] = ((uint32_t)*reinterpret_cast<uint16_t*>(&h1) << 16) |
                    *reinterpret_cast<uint16_t*>(&h0);
            pl[q] = ((uint32_t)*reinterpret_cast<uint16_t*>(&l1) << 16) |
                    *reinterpret_cast<uint16_t*>(&l0);
        }
        *reinterpret_cast<uint4*>(g_xh + (size_t)row * EE + e0) = vh;
        *reinterpret_cast<uint4*>(g_xl + (size_t)row * EE + e0) = vl;
    } else if (bid < 768) {
        int f = bid - 512;
        const float* w = (tid < 256) ? w1 : w2;
        __nv_bfloat16* wh = (tid < 256) ? g_wh1 : g_wh2;
        __nv_bfloat16* wl = (tid < 256) ? g_wl1 : g_wl2;
        int e = tid & 255;
#pragma unroll
        for (int k = 0; k < 3; ++k) {
            __nv_bfloat16 hi, lo;
            split_bf16(w[f * KTOT + e * 3 + k], hi, lo);
            wh[f * KTOT + k * 256 + e] = hi;
            wl[f * KTOT + k * 256 + e] = lo;
        }
    } else {
        int n = bid - 768;
        int t = tid;                    // 512 threads
        __shared__ int s[512];
        int d = target[n * LL + t];
        s[t] = d;
        __syncthreads();
        for (int off = 1; off < 512; off <<= 1) {
            int v = (t >= off) ? s[t - off] : 0;
            __syncthreads();
            s[t] += v;
            __syncthreads();
        }
        int cum = s[t], start = cum - d;
        for (int i = t; i < MM; i += 512) g_idx[n * MM + i] = -1;
        __syncthreads();
        for (int u = start; u < cum; ++u) g_idx[n * MM + u] = t;
    }
}

// ---------------- gather helper: one row, 32 lanes, 2 float4 each ------------
__device__ __forceinline__ void gather_row(const float* __restrict__ x,
                                           float* __restrict__ out,
                                           int grow, int lane) {
    int j = g_idx[grow];
    float4 v0 = make_float4(0.f, 0.f, 0.f, 0.f), v1 = v0;
    if (j >= 0) {
        const float4* src = reinterpret_cast<const float4*>(
            x + (size_t)((grow >> 12) * LL + j) * EE);
        v0 = __ldg(src + lane * 2);
        v1 = __ldg(src + lane * 2 + 1);
    }
    float4* dst = reinterpret_cast<float4*>(out + (size_t)grow * EE);
    __stwt(dst + lane * 2, v0);
    __stwt(dst + lane * 2 + 1, v1);
}

// ---------------- 3xBF16 HMMA GEMM + fused LN/ReLU + warp-specialized gather -
// grid = 148: CTAs 0-127 = GEMM (8 warps, named barrier 1) + 4 gather warps
// (192 rows); CTAs 128-147 = pure gather (12 warps, 410 rows).
// A is compact [row][256]; chunk c -> k-slot c/4, e-range (c%4)*64, src row
// shifted by slot-1 with cp.async zero-fill at sequence boundaries.
// SECOND=0: epilogue stores h1 (hi/lo); SECOND=1: dur_out.
template <int SECOND>
__global__ void __launch_bounds__(384) gemm_ln_kernel(
    const float* __restrict__ bias, const float* __restrict__ gamma,
    const float* __restrict__ beta, const float* __restrict__ lw,
    const float* __restrict__ lbp, float* __restrict__ durout,
    const float* __restrict__ x, float* __restrict__ out)
{
    extern __shared__ char smem[];
    uint32_t sb = smem_u32(smem);
    int tid = threadIdx.x;
    int bid = blockIdx.x;

    if (bid >= GEMM_CTAS) {
        // ---------------- pure gather CTA: all 12 warps ----------------
        int w = tid >> 5, lane = tid & 31;
        int base = SECOND * GROWS_HALF + ROWS_GEMM_TOTAL +
                   (bid - GEMM_CTAS) * ROWS_PER_GATH_CTA;
        int lim = SECOND * GROWS_HALF + GROWS_HALF;
        for (int r = w; r < ROWS_PER_GATH_CTA; r += 12) {
            int grow = base + r;
            if (grow < lim) gather_row(x, out, grow, lane);
        }
        return;
    }

    if (tid >= 256) {
        // ---------------- gather warps in GEMM CTA (48 rows each) --------
        int gt = tid - 256;
        int w = gt >> 5, lane = gt & 31;
        int rbase = SECOND * GROWS_HALF + bid * ROWS_PER_GEMM_CTA + w * 48;
#pragma unroll 4
        for (int rr = 0; rr < 48; ++rr) gather_row(x, out, rbase + rr, lane);
        return;
    }

    // ---------------- GEMM warp group (tid < 256) ----------------
    int wid = tid >> 5, lane = tid & 31;
    int m0 = bid * 64;
    int wm = wid & 1, wn = wid >> 1;
    int g = lane >> 2, t = lane & 3;
    const __nv_bfloat16* Ah = SECOND ? g_h1h : g_xh;
    const __nv_bfloat16* Al = SECOND ? g_h1l : g_xl;
    const __nv_bfloat16* Bh = SECOND ? g_wh2 : g_wh1;
    const __nv_bfloat16* Bl = SECOND ? g_wl2 : g_wl1;

    {
        float* pp = reinterpret_cast<float*>(smem + SM_PAR);
        pp[tid] = bias[tid];
        pp[256 + tid] = gamma[tid];
        pp[512 + tid] = beta[tid];
        pp[768 + tid] = SECOND ? lw[tid] : 0.f;
    }

    int a_row = (((lane >> 3) & 1) << 3) + (lane & 7);
    int a_kb  = (lane >> 4) << 4;
    int b_row = ((lane >> 4) << 3) + (lane & 7);
    int b_kb  = ((lane >> 3) & 1) << 4;

    auto issue_chunk = [&](int c, int buf) {
        uint32_t sa = sb + buf * STAGE;
        uint32_t sbm = sa + ASZ;
        int slot = c >> 2;                      // conv k index 0..2
        int e0c = (c & 3) << 6;                 // 0,64,128,192 (bf16 elems)
#pragma unroll
        for (int i = 0; i < 2; ++i) {
            int lin = tid + (i << 8);
            int row = lin >> 3, seg = lin & 7;
            int grow = m0 + row;
            int l = grow & 511;
            int sl = l + slot - 1;
            uint32_t ok = (sl >= 0 && sl < LL) ? 16u : 0u;
            size_t srow = ok ? (size_t)(grow + slot - 1) : 0;
            const char* srch = reinterpret_cast<const char*>(Ah) +
                               (srow * EE + e0c) * 2 + seg * 16;
            const char* srcl = reinterpret_cast<const char*>(Al) +
                               (srow * EE + e0c) * 2 + seg * 16;
            cp16z(sa + row * ROWB + seg * 16, srch, ok);
            cp16z(sa + (64 + row) * ROWB + seg * 16, srcl, ok);
        }
        size_t boff = (size_t)c * KC * 2;
        const char* gBh = reinterpret_cast<const char*>(Bh) + boff;
        const char* gBl = reinterpret_cast<const char*>(Bl) + boff;
#pragma unroll
        for (int i = 0; i < 8; ++i) {
            int lin = tid + (i << 8);
            int row = lin >> 3, seg = lin & 7;
            cp16(sbm + row * ROWB + seg * 16, gBh + (size_t)row * 1536 + seg * 16);
            cp16(sbm + (256 + row) * ROWB + seg * 16, gBl + (size_t)row * 1536 + seg * 16);
        }
        CP_COMMIT();
    };

    float acc[2][8][4];
#pragma unroll
    for (int mt = 0; mt < 2; ++mt)
#pragma unroll
        for (int nt = 0; nt < 8; ++nt)
#pragma unroll
            for (int q = 0; q < 4; ++q) acc[mt][nt][q] = 0.f;

    issue_chunk(0, 0);
    for (int c = 0; c < NCHUNK; ++c) {
        int buf = c & 1;
        if (c + 1 < NCHUNK) {
            issue_chunk(c + 1, buf ^ 1);
            cp_wait<1>();
        } else {
            cp_wait<0>();
        }
        BARG();
        uint32_t abase = sb + buf * STAGE;
        uint32_t bbase = abase + ASZ;
#pragma unroll
        for (int ks = 0; ks < 4; ++ks) {
            int k0 = ks * 16;
            uint32_t fAh[2][4], fAl[2][4];
            uint32_t fBh[8][2], fBl[8][2];
#pragma unroll
            for (int mt = 0; mt < 2; ++mt) {
                uint32_t ra = abase + (wm * 32 + mt * 16 + a_row) * ROWB + k0 * 2 + a_kb;
                ldsm4(fAh[mt], ra);
                ldsm4(fAl[mt], ra + 64 * ROWB);
            }
#pragma unroll
            for (int np = 0; np < 4; ++np) {
                uint32_t rb = bbase + (wn * 64 + np * 16 + b_row) * ROWB + k0 * 2 + b_kb;
                uint32_t r[4];
                ldsm4(r, rb);
                fBh[2 * np][0] = r[0]; fBh[2 * np][1] = r[1];
                fBh[2 * np + 1][0] = r[2]; fBh[2 * np + 1][1] = r[3];
                ldsm4(r, rb + 256 * ROWB);
                fBl[2 * np][0] = r[0]; fBl[2 * np][1] = r[1];
                fBl[2 * np + 1][0] = r[2]; fBl[2 * np + 1][1] = r[3];
            }
#pragma unroll
            for (int mt = 0; mt < 2; ++mt) {
#pragma unroll
                for (int nt = 0; nt < 8; ++nt)
                    mma_bf16(acc[mt][nt], fAh[mt][0], fAh[mt][1], fAh[mt][2], fAh[mt][3],
                             fBh[nt][0], fBh[nt][1]);
#pragma unroll
                for (int nt = 0; nt < 8; ++nt)
                    mma_bf16(acc[mt][nt], fAh[mt][0], fAh[mt][1], fAh[mt][2], fAh[mt][3],
                             fBl[nt][0], fBl[nt][1]);
#pragma unroll
                for (int nt = 0; nt < 8; ++nt)
                    mma_bf16(acc[mt][nt], fAl[mt][0], fAl[mt][1], fAl[mt][2], fAl[mt][3],
                             fBh[nt][0], fBh[nt][1]);
            }
        }
        BARG();
    }

    // ---------------- epilogue ----------------
    float* ot = reinterpret_cast<float*>(smem);   // [64][260] fp32
#pragma unroll
    for (int mt = 0; mt < 2; ++mt)
#pragma unroll
        for (int nt = 0; nt < 8; ++nt) {
            int m = wm * 32 + mt * 16 + g;
            int n = wn * 64 + nt * 8 + 2 * t;
            *reinterpret_cast<float2*>(ot + m * 260 + n) =
                make_float2(acc[mt][nt][0], acc[mt][nt][1]);
            *reinterpret_cast<float2*>(ot + (m + 8) * 260 + n) =
                make_float2(acc[mt][nt][2], acc[mt][nt][3]);
        }
    BARG();

    const float* pb = reinterpret_cast<const float*>(smem + SM_PAR);
    const float* pg = pb + 256;
    const float* pe = pb + 512;
    const float* pl = pb + 768;
    float2* mus = reinterpret_cast<float2*>(smem + SM_MU);

    if (tid < 64) {
        const float* rowp = ot + tid * 260;
        float s = 0.f, ss = 0.f;
#pragma unroll 4
        for (int j = 0; j < 256; j += 4) {
            float4 v4 = *reinterpret_cast<const float4*>(rowp + j);
            float h0 = v4.x + pb[j], h1 = v4.y + pb[j + 1];
            float h2 = v4.z + pb[j + 2], h3 = v4.w + pb[j + 3];
            s += h0 + h1 + h2 + h3;
            ss += h0 * h0 + h1 * h1 + h2 * h2 + h3 * h3;
        }
        float mu = s * (1.f / 256.f);
        float var = ss * (1.f / 256.f) - mu * mu;
        mus[tid] = make_float2(mu, rsqrtf(var + 1e-5f));
    }
    BARG();

    if (!SECOND) {
        int row_l = tid & 63;
        int part = tid >> 6;
        int row = m0 + row_l;
        float2 mr = mus[row_l];
        float mu = mr.x, rs = mr.y;
        const float* rowp = ot + row_l * 260;
#pragma unroll
        for (int jj = 0; jj < 64; jj += 8) {
            int j = part * 64 + jj;
            uint32_t wh[4], wl[4];
#pragma unroll
            for (int q = 0; q < 4; ++q) {
                float v0 = rowp[j + 2 * q] + pb[j + 2 * q];
                float v1 = rowp[j + 2 * q + 1] + pb[j + 2 * q + 1];
                float y0 = fmaxf(0.f, (v0 - mu) * rs * pg[j + 2 * q] + pe[j + 2 * q]);
                float y1 = fmaxf(0.f, (v1 - mu) * rs * pg[j + 2 * q + 1] + pe[j + 2 * q + 1]);
                __nv_bfloat16 h0, l0, h1, l1;
                split_bf16(y0, h0, l0);
                split_bf16(y1, h1, l1);
                wh[q] = ((uint32_t)*reinterpret_cast<uint16_t*>(&h1) << 16) |
                        *reinterpret_cast<uint16_t*>(&h0);
                wl[q] = ((uint32_t)*reinterpret_cast<uint16_t*>(&l1) << 16) |
                        *reinterpret_cast<uint16_t*>(&l0);
            }
            *reinterpret_cast<uint4*>(g_h1h + (size_t)row * FF + j) =
                make_uint4(wh[0], wh[1], wh[2], wh[3]);
            *reinterpret_cast<uint4*>(g_h1l + (size_t)row * FF + j) =
                make_uint4(wl[0], wl[1], wl[2], wl[3]);
        }
    } else {
        if (tid < 64) {
            float2 mr = mus[tid];
            float mu = mr.x, rs = mr.y;
            const float* rowp = ot + tid * 260;
            float dacc = 0.f;
#pragma unroll 4
            for (int j = 0; j < 256; ++j) {
                float y = fmaxf(0.f, (rowp[j] + pb[j] - mu) * rs * pg[j] + pe[j]);
                dacc += y * pl[j];
            }
            durout[m0 + tid] = fmaxf(0.f, dacc + *lbp);
        }
    }
}

// ---------------- launch ----------------
extern "C" void kernel_launch(void* const* d_in, const int* in_sizes, int n_in,
                              void* d_out, int out_size) {
    const float* x   = (const float*)d_in[0];
    const float* c1w = (const float*)d_in[1];
    const float* c1b = (const float*)d_in[2];
    const float* l1g = (const float*)d_in[3];
    const float* l1b = (const float*)d_in[4];
    const float* c2w = (const float*)d_in[5];
    const float* c2b = (const float*)d_in[6];
    const float* l2g = (const float*)d_in[7];
    const float* l2b = (const float*)d_in[8];
    const float* lw  = (const float*)d_in[9];
    const float* lb  = (const float*)d_in[10];
    const int* target = (const int*)d_in[11];
    float* out = (float*)d_out;

    cudaFuncSetAttribute(gemm_ln_kernel<0>, cudaFuncAttributeMaxDynamicSharedMemorySize, SM_TOTAL);
    cudaFuncSetAttribute(gemm_ln_kernel<1>, cudaFuncAttributeMaxDynamicSharedMemorySize, SM_TOTAL);

    prep_kernel<<<784, 512>>>(x, c1w, c2w, target);
    gemm_ln_kernel<0><<<GRID, 384, SM_TOTAL>>>(c1b, l1g, l1b, lw, lb, nullptr, x, out);
    gemm_ln_kernel<1><<<GRID, 384, SM_TOTAL>>>(c2b, l2g, l2b, lw, lb, out + OUT_ELEMS, x, out);
}

// round 17
// speedup vs baseline: 1.9351x; 1.0217x over previous
#include <cuda_runtime.h>
#include <cuda_bf16.h>
#include <cstdint>

#define NB 16
#define LL 512
#define EE 256
#define FF 256
#define MM 4096
#define OUT_ELEMS (NB * MM * EE)   // 16777216
#define KTOT 768
#define NROWS (NB * LL)            // 8192
#define KC 64
#define NCHUNK (KTOT / KC)         // 12
#define PADK 72
#define ROWB (PADK * 2)            // 144 bytes
#define GROWS_HALF (NB * MM / 2)   // 32768
#define GEMM_CTAS 128
#define GATH_CTAS 20
#define GRID (GEMM_CTAS + GATH_CTAS)
#define ROWS_PER_GEMM_CTA 192
#define ROWS_GEMM_TOTAL (GEMM_CTAS * ROWS_PER_GEMM_CTA)
#define ROWS_PER_GATH_CTA 410

// A-resident layout (SECOND==0): row stride 528 B (132 words -> conflict-free)
#define AROWB 528
#define APLANE (66 * AROWB)            // 34848 per plane

// ---------------- scratch ----------------
__device__ __nv_bfloat16 g_h1h[NROWS * FF];   // conv1 out hi
__device__ __nv_bfloat16 g_h1l[NROWS * FF];   // conv1 out lo
__device__ __nv_bfloat16 g_wh1[FF * KTOT];
__device__ __nv_bfloat16 g_wl1[FF * KTOT];
__device__ __nv_bfloat16 g_wh2[FF * KTOT];
__device__ __nv_bfloat16 g_wl2[FF * KTOT];
__device__ int           g_idx[NB * MM];

// ---------------- smem layouts ----------------
#define ASZ   (128 * ROWB)             // SECOND==1 A stage
#define BSZ   (512 * ROWB)             // 73728 (B hi+lo)
#define STAGE1 (ASZ + BSZ)             // 92160  (SECOND==1 stage)
// SECOND==0: B0 @0, B1 @BSZ, A @2*BSZ (2 planes), PAR, MU
#define SM_A0    (2 * BSZ)             // 147456
#define PAR0     (SM_A0 + 2 * APLANE)  // 217152
#define MU0      (PAR0 + 4096)         // 221248
#define TOTAL0   (MU0 + 512)           // 221760
// SECOND==1: stages @0,@STAGE1, PAR, MU
#define PAR1     (2 * STAGE1)          // 184320
#define MU1      (PAR1 + 4096)
#define TOTAL1   (MU1 + 512)           // 188928

// ---------------- helpers ----------------
__device__ __forceinline__ uint32_t smem_u32(const void* p) {
    uint32_t a;
    asm("{ .reg .u64 t; cvta.to.shared.u64 t, %1; cvt.u32.u64 %0, t; }" : "=r"(a) : "l"(p));
    return a;
}
__device__ __forceinline__ void cp16(uint32_t dst, const void* src) {
    asm volatile("cp.async.cg.shared.global [%0], [%1], 16;" :: "r"(dst), "l"(src));
}
__device__ __forceinline__ void cp16z(uint32_t dst, const void* src, uint32_t src_sz) {
    asm volatile("cp.async.cg.shared.global [%0], [%1], 16, %2;"
                 :: "r"(dst), "l"(src), "r"(src_sz));
}
#define CP_COMMIT() asm volatile("cp.async.commit_group;" ::: "memory")
template <int N>
__device__ __forceinline__ void cp_wait() {
    asm volatile("cp.async.wait_group %0;" :: "n"(N) : "memory");
}
#define BARG() asm volatile("bar.sync 1, 256;" ::: "memory")
__device__ __forceinline__ void ldsm4(uint32_t* r, uint32_t addr) {
    asm volatile("ldmatrix.sync.aligned.m8n8.x4.shared.b16 {%0,%1,%2,%3}, [%4];"
                 : "=r"(r[0]), "=r"(r[1]), "=r"(r[2]), "=r"(r[3]) : "r"(addr));
}
__device__ __forceinline__ void mma_bf16(float* d, uint32_t a0, uint32_t a1,
                                         uint32_t a2, uint32_t a3,
                                         uint32_t b0, uint32_t b1) {
    asm("mma.sync.aligned.m16n8k16.row.col.f32.bf16.bf16.f32 "
        "{%0,%1,%2,%3}, {%4,%5,%6,%7}, {%8,%9}, {%0,%1,%2,%3};"
        : "+f"(d[0]), "+f"(d[1]), "+f"(d[2]), "+f"(d[3])
        : "r"(a0), "r"(a1), "r"(a2), "r"(a3), "r"(b0), "r"(b1));
}
__device__ __forceinline__ void split_bf16(float v, __nv_bfloat16& hi, __nv_bfloat16& lo) {
    hi = __float2bfloat16(v);
    lo = __float2bfloat16(v - __bfloat162float(hi));
}
__device__ __forceinline__ uint32_t pack_hi(float a, float b, uint32_t& lo_out) {
    __nv_bfloat16 h0, l0, h1, l1;
    split_bf16(a, h0, l0);
    split_bf16(b, h1, l1);
    lo_out = ((uint32_t)*reinterpret_cast<uint16_t*>(&l1) << 16) |
             *reinterpret_cast<uint16_t*>(&l0);
    return ((uint32_t)*reinterpret_cast<uint16_t*>(&h1) << 16) |
           *reinterpret_cast<uint16_t*>(&h0);
}

// ---------------- prep: weights + idx only ----------------
// blocks [0,256): prep_w (f = bid); [256,272): build_idx (n = bid-256).
__global__ void __launch_bounds__(512) prep_kernel(
    const float* __restrict__ w1, const float* __restrict__ w2,
    const int* __restrict__ target)
{
    int bid = blockIdx.x, tid = threadIdx.x;
    if (bid < 256) {
        int f = bid;
        const float* w = (tid < 256) ? w1 : w2;
        __nv_bfloat16* wh = (tid < 256) ? g_wh1 : g_wh2;
        __nv_bfloat16* wl = (tid < 256) ? g_wl1 : g_wl2;
        int e = tid & 255;
#pragma unroll
        for (int k = 0; k < 3; ++k) {
            __nv_bfloat16 hi, lo;
            split_bf16(w[f * KTOT + e * 3 + k], hi, lo);
            wh[f * KTOT + k * 256 + e] = hi;
            wl[f * KTOT + k * 256 + e] = lo;
        }
    } else {
        int n = bid - 256;
        int t = tid;
        __shared__ int s[512];
        int d = target[n * LL + t];
        s[t] = d;
        __syncthreads();
        for (int off = 1; off < 512; off <<= 1) {
            int v = (t >= off) ? s[t - off] : 0;
            __syncthreads();
            s[t] += v;
            __syncthreads();
        }
        int cum = s[t], start = cum - d;
        for (int i = t; i < MM; i += 512) g_idx[n * MM + i] = -1;
        __syncthreads();
        for (int u = start; u < cum; ++u) g_idx[n * MM + u] = t;
    }
}

// ---------------- gather helper ----------------
__device__ __forceinline__ void gather_row(const float* __restrict__ x,
                                           float* __restrict__ out,
                                           int grow, int lane) {
    int j = g_idx[grow];
    float4 v0 = make_float4(0.f, 0.f, 0.f, 0.f), v1 = v0;
    if (j >= 0) {
        const float4* src = reinterpret_cast<const float4*>(
            x + (size_t)((grow >> 12) * LL + j) * EE);
        v0 = __ldg(src + lane * 2);
        v1 = __ldg(src + lane * 2 + 1);
    }
    float4* dst = reinterpret_cast<float4*>(out + (size_t)grow * EE);
    __stwt(dst + lane * 2, v0);
    __stwt(dst + lane * 2 + 1, v1);
}

// ---------------- 3xBF16 HMMA GEMM + fused LN/ReLU + gather ------------------
// SECOND==0: A converted in-kernel from x into persistent smem (66 rows incl.
// halo, boundary rows zeroed); no A staging in mainloop.
// SECOND==1: A from g_h1 planes via cp16z (R16 path, unchanged).
template <int SECOND>
__global__ void __launch_bounds__(384) gemm_ln_kernel(
    const float* __restrict__ bias, const float* __restrict__ gamma,
    const float* __restrict__ beta, const float* __restrict__ lw,
    const float* __restrict__ lbp, float* __restrict__ durout,
    const float* __restrict__ x, float* __restrict__ out)
{
    extern __shared__ char smem[];
    uint32_t sb = smem_u32(smem);
    int tid = threadIdx.x;
    int bid = blockIdx.x;

    if (bid >= GEMM_CTAS) {
        int w = tid >> 5, lane = tid & 31;
        int base = SECOND * GROWS_HALF + ROWS_GEMM_TOTAL +
                   (bid - GEMM_CTAS) * ROWS_PER_GATH_CTA;
        int lim = SECOND * GROWS_HALF + GROWS_HALF;
        for (int r = w; r < ROWS_PER_GATH_CTA; r += 12) {
            int grow = base + r;
            if (grow < lim) gather_row(x, out, grow, lane);
        }
        return;
    }
    if (tid >= 256) {
        int gt = tid - 256;
        int w = gt >> 5, lane = gt & 31;
        int rbase = SECOND * GROWS_HALF + bid * ROWS_PER_GEMM_CTA + w * 48;
#pragma unroll 4
        for (int rr = 0; rr < 48; ++rr) gather_row(x, out, rbase + rr, lane);
        return;
    }

    // ---------------- GEMM warp group ----------------
    int wid = tid >> 5, lane = tid & 31;
    int m0 = bid * 64;
    int wm = wid & 1, wn = wid >> 1;
    int g = lane >> 2, t = lane & 3;
    const __nv_bfloat16* Bh = SECOND ? g_wh2 : g_wh1;
    const __nv_bfloat16* Bl = SECOND ? g_wl2 : g_wl1;

    constexpr uint32_t PAR_OFF = SECOND ? PAR1 : PAR0;
    constexpr uint32_t MU_OFF  = SECOND ? MU1  : MU0;

    {
        float* pp = reinterpret_cast<float*>(smem + PAR_OFF);
        pp[tid] = bias[tid];
        pp[256 + tid] = gamma[tid];
        pp[512 + tid] = beta[tid];
        pp[768 + tid] = SECOND ? lw[tid] : 0.f;
    }

    int a_row = (((lane >> 3) & 1) << 3) + (lane & 7);
    int a_kb  = (lane >> 4) << 4;
    int b_row = ((lane >> 4) << 3) + (lane & 7);
    int b_kb  = ((lane >> 3) & 1) << 4;

    auto issue_chunk = [&](int c, int buf) {
        uint32_t sbm = SECOND ? (sb + buf * STAGE1 + ASZ) : (sb + buf * BSZ);
        if (SECOND) {
            uint32_t sa = sb + buf * STAGE1;
            int slot = c >> 2;
            int e0c = (c & 3) << 6;
#pragma unroll
            for (int i = 0; i < 2; ++i) {
                int lin = tid + (i << 8);
                int row = lin >> 3, seg = lin & 7;
                int grow = m0 + row;
                int l = grow & 511;
                int sl = l + slot - 1;
                uint32_t ok = (sl >= 0 && sl < LL) ? 16u : 0u;
                size_t srow = ok ? (size_t)(grow + slot - 1) : 0;
                const char* srch = reinterpret_cast<const char*>(g_h1h) +
                                   (srow * FF + e0c) * 2 + seg * 16;
                const char* srcl = reinterpret_cast<const char*>(g_h1l) +
                                   (srow * FF + e0c) * 2 + seg * 16;
                cp16z(sa + row * ROWB + seg * 16, srch, ok);
                cp16z(sa + (64 + row) * ROWB + seg * 16, srcl, ok);
            }
        }
        size_t boff = (size_t)c * KC * 2;
        const char* gBh = reinterpret_cast<const char*>(Bh) + boff;
        const char* gBl = reinterpret_cast<const char*>(Bl) + boff;
#pragma unroll
        for (int i = 0; i < 8; ++i) {
            int lin = tid + (i << 8);
            int row = lin >> 3, seg = lin & 7;
            cp16(sbm + row * ROWB + seg * 16, gBh + (size_t)row * 1536 + seg * 16);
            cp16(sbm + (256 + row) * ROWB + seg * 16, gBl + (size_t)row * 1536 + seg * 16);
        }
        CP_COMMIT();
    };

    float acc[2][8][4];
#pragma unroll
    for (int mt = 0; mt < 2; ++mt)
#pragma unroll
        for (int nt = 0; nt < 8; ++nt)
#pragma unroll
            for (int q = 0; q < 4; ++q) acc[mt][nt][q] = 0.f;

    issue_chunk(0, 0);

    if (!SECOND) {
        // convert 66 input rows (m0-1 .. m0+64) fp32 -> hi/lo smem planes,
        // overlapped with chunk 0's B cp.async flight.
        int l0 = m0 & 511;
        for (int i = tid; i < 66 * 32; i += 256) {
            int r = i >> 5, seg = i & 31;          // seg = 8 elems (32 B fp32)
            int l = l0 + r - 1;
            uint4 vh = make_uint4(0u, 0u, 0u, 0u), vl = vh;
            if (l >= 0 && l < LL) {
                const float* xr = x + ((size_t)(m0 + r - 1) * EE + seg * 8);
                float4 f0 = *reinterpret_cast<const float4*>(xr);
                float4 f1 = *reinterpret_cast<const float4*>(xr + 4);
                vh.x = pack_hi(f0.x, f0.y, vl.x);
                vh.y = pack_hi(f0.z, f0.w, vl.y);
                vh.z = pack_hi(f1.x, f1.y, vl.z);
                vh.w = pack_hi(f1.z, f1.w, vl.w);
            }
            uint32_t off = r * AROWB + seg * 16;
            *reinterpret_cast<uint4*>(smem + SM_A0 + off) = vh;
            *reinterpret_cast<uint4*>(smem + SM_A0 + APLANE + off) = vl;
        }
    }

    for (int c = 0; c < NCHUNK; ++c) {
        int buf = c & 1;
        if (c + 1 < NCHUNK) {
            issue_chunk(c + 1, buf ^ 1);
            cp_wait<1>();
        } else {
            cp_wait<0>();
        }
        BARG();
        uint32_t bbase = SECOND ? (sb + buf * STAGE1 + ASZ) : (sb + buf * BSZ);
        uint32_t abase = SECOND ? (sb + buf * STAGE1) : 0;
        int slot = c >> 2;
        int e0c = (c & 3) << 7;                    // byte offset: (c&3)*64*2
#pragma unroll
        for (int ks = 0; ks < 4; ++ks) {
            int k0 = ks * 16;
            uint32_t fAh[2][4], fAl[2][4];
            uint32_t fBh[8][2], fBl[8][2];
#pragma unroll
            for (int mt = 0; mt < 2; ++mt) {
                uint32_t ra;
                if (SECOND) {
                    ra = abase + (wm * 32 + mt * 16 + a_row) * ROWB + k0 * 2 + a_kb;
                    ldsm4(fAh[mt], ra);
                    ldsm4(fAl[mt], ra + 64 * ROWB);
                } else {
                    ra = sb + SM_A0 + (wm * 32 + mt * 16 + a_row + slot) * AROWB
                         + e0c + k0 * 2 + a_kb;
                    ldsm4(fAh[mt], ra);
                    ldsm4(fAl[mt], ra + APLANE);
                }
            }
#pragma unroll
            for (int np = 0; np < 4; ++np) {
                uint32_t rb = bbase + (wn * 64 + np * 16 + b_row) * ROWB + k0 * 2 + b_kb;
                uint32_t r[4];
                ldsm4(r, rb);
                fBh[2 * np][0] = r[0]; fBh[2 * np][1] = r[1];
                fBh[2 * np + 1][0] = r[2]; fBh[2 * np + 1][1] = r[3];
                ldsm4(r, rb + 256 * ROWB);
                fBl[2 * np][0] = r[0]; fBl[2 * np][1] = r[1];
                fBl[2 * np + 1][0] = r[2]; fBl[2 * np + 1][1] = r[3];
            }
#pragma unroll
            for (int mt = 0; mt < 2; ++mt) {
#pragma unroll
                for (int nt = 0; nt < 8; ++nt)
                    mma_bf16(acc[mt][nt], fAh[mt][0], fAh[mt][1], fAh[mt][2], fAh[mt][3],
                             fBh[nt][0], fBh[nt][1]);
#pragma unroll
                for (int nt = 0; nt < 8; ++nt)
                    mma_bf16(acc[mt][nt], fAh[mt][0], fAh[mt][1], fAh[mt][2], fAh[mt][3],
                             fBl[nt][0], fBl[nt][1]);
#pragma unroll
                for (int nt = 0; nt < 8; ++nt)
                    mma_bf16(acc[mt][nt], fAl[mt][0], fAl[mt][1], fAl[mt][2], fAl[mt][3],
                             fBh[nt][0], fBh[nt][1]);
            }
        }
        BARG();
    }

    // ---------------- epilogue ----------------
    float* ot = reinterpret_cast<float*>(smem);   // [64][260] fp32, reuses B0
#pragma unroll
    for (int mt = 0; mt < 2; ++mt)
#pragma unroll
        for (int nt = 0; nt < 8; ++nt) {
            int m = wm * 32 + mt * 16 + g;
            int n = wn * 64 + nt * 8 + 2 * t;
            *reinterpret_cast<float2*>(ot + m * 260 + n) =
                make_float2(acc[mt][nt][0], acc[mt][nt][1]);
            *reinterpret_cast<float2*>(ot + (m + 8) * 260 + n) =
                make_float2(acc[mt][nt][2], acc[mt][nt][3]);
        }
    BARG();

    const float* pb = reinterpret_cast<const float*>(smem + PAR_OFF);
    const float* pg = pb + 256;
    const float* pe = pb + 512;
    const float* pl = pb + 768;
    float2* mus = reinterpret_cast<float2*>(smem + MU_OFF);

    if (tid < 64) {
        const float* rowp = ot + tid * 260;
        float s = 0.f, ss = 0.f;
#pragma unroll 4
        for (int j = 0; j < 256; j += 4) {
            float4 v4 = *reinterpret_cast<const float4*>(rowp + j);
            float h0 = v4.x + pb[j], h1 = v4.y + pb[j + 1];
            float h2 = v4.z + pb[j + 2], h3 = v4.w + pb[j + 3];
            s += h0 + h1 + h2 + h3;
            ss += h0 * h0 + h1 * h1 + h2 * h2 + h3 * h3;
        }
        float mu = s * (1.f / 256.f);
        float var = ss * (1.f / 256.f) - mu * mu;
        mus[tid] = make_float2(mu, rsqrtf(var + 1e-5f));
    }
    BARG();

    if (!SECOND) {
        int row_l = tid & 63;
        int part = tid >> 6;
        int row = m0 + row_l;
        float2 mr = mus[row_l];
        float mu = mr.x, rs = mr.y;
        const float* rowp = ot + row_l * 260;
#pragma unroll
        for (int jj = 0; jj < 64; jj += 8) {
            int j = part * 64 + jj;
            uint32_t wh[4], wl[4];
#pragma unroll
            for (int q = 0; q < 4; ++q) {
                float v0 = rowp[j + 2 * q] + pb[j + 2 * q];
                float v1 = rowp[j + 2 * q + 1] + pb[j + 2 * q + 1];
                float y0 = fmaxf(0.f, (v0 - mu) * rs * pg[j + 2 * q] + pe[j + 2 * q]);
                float y1 = fmaxf(0.f, (v1 - mu) * rs * pg[j + 2 * q + 1] + pe[j + 2 * q + 1]);
                wh[q] = pack_hi(y0, y1, wl[q]);
            }
            *reinterpret_cast<uint4*>(g_h1h + (size_t)row * FF + j) =
                make_uint4(wh[0], wh[1], wh[2], wh[3]);
            *reinterpret_cast<uint4*>(g_h1l + (size_t)row * FF + j) =
                make_uint4(wl[0], wl[1], wl[2], wl[3]);
        }
    } else {
        if (tid < 64) {
            float2 mr = mus[tid];
            float mu = mr.x, rs = mr.y;
            const float* rowp = ot + tid * 260;
            float dacc = 0.f;
#pragma unroll 4
            for (int j = 0; j < 256; ++j) {
                float y = fmaxf(0.f, (rowp[j] + pb[j] - mu) * rs * pg[j] + pe[j]);
                dacc += y * pl[j];
            }
            durout[m0 + tid] = fmaxf(0.f, dacc + *lbp);
        }
    }
}

// ---------------- launch ----------------
extern "C" void kernel_launch(void* const* d_in, const int* in_sizes, int n_in,
                              void* d_out, int out_size) {
    const float* x   = (const float*)d_in[0];
    const float* c1w = (const float*)d_in[1];
    const float* c1b = (const float*)d_in[2];
    const float* l1g = (const float*)d_in[3];
    const float* l1b = (const float*)d_in[4];
    const float* c2w = (const float*)d_in[5];
    const float* c2b = (const float*)d_in[6];
    const float* l2g = (const float*)d_in[7];
    const float* l2b = (const float*)d_in[8];
    const float* lw  = (const float*)d_in[9];
    const float* lb  = (const float*)d_in[10];
    const int* target = (const int*)d_in[11];
    float* out = (float*)d_out;

    cudaFuncSetAttribute(gemm_ln_kernel<0>, cudaFuncAttributeMaxDynamicSharedMemorySize, TOTAL0);
    cudaFuncSetAttribute(gemm_ln_kernel<1>, cudaFuncAttributeMaxDynamicSharedMemorySize, TOTAL1);

    prep_kernel<<<272, 512>>>(c1w, c2w, target);
    gemm_ln_kernel<0><<<GRID, 384, TOTAL0>>>(c1b, l1g, l1b, lw, lb, nullptr, x, out);
    gemm_ln_kernel<1><<<GRID, 384, TOTAL1>>>(c2b, l2g, l2b, lw, lb, out + OUT_ELEMS, x, out);
}